// round 12
// baseline (speedup 1.0000x reference)
#include <cuda_runtime.h>
#include <cuda_bf16.h>
#include <cstdint>

typedef unsigned long long ull;

#define NW   4096
#define NHD  6
#define HD   32
#define CDIM 192
#define WS2  64

// smem tile layout (bf16, row pitch 200 elems => 400B rows, ldmatrix conflict-free)
#define PITCH  200
#define OFF_AH 0
#define OFF_AL 51200
#define OFF_BH 102400
#define OFF_BL 128000
#define GEMM_SMEM 153600

// ---- scratch ----
__device__ float g_qkv[(size_t)3 * NW * NHD * WS2 * HD];   // [which][w][h][t][d]
__device__ float g_att[(size_t)NW * WS2 * CDIM];           // [w][t][h*32+d]
__device__ __nv_bfloat16 g_wqh[576 * 192], g_wql[576 * 192];  // qkv weights hi/lo (q rows pre-scaled)
__device__ __nv_bfloat16 g_wph[192 * 192], g_wpl[192 * 192];  // proj weights hi/lo

// ================= mma / ldmatrix helpers =================
__device__ __forceinline__ uint32_t smem_to_u32(const void* p) {
    uint32_t a;
    asm("{ .reg .u64 t; cvta.to.shared.u64 t, %1; cvt.u32.u64 %0, t; }" : "=r"(a) : "l"(p));
    return a;
}
__device__ __forceinline__ void ldsm4(uint32_t& r0, uint32_t& r1, uint32_t& r2, uint32_t& r3,
                                      uint32_t addr) {
    asm volatile("ldmatrix.sync.aligned.m8n8.x4.shared.b16 {%0,%1,%2,%3}, [%4];"
                 : "=r"(r0), "=r"(r1), "=r"(r2), "=r"(r3) : "r"(addr));
}
__device__ __forceinline__ void mma16816(float* c, uint32_t a0, uint32_t a1, uint32_t a2,
                                         uint32_t a3, uint32_t b0, uint32_t b1) {
    asm volatile("mma.sync.aligned.m16n8k16.row.col.f32.bf16.bf16.f32 "
                 "{%0,%1,%2,%3}, {%4,%5,%6,%7}, {%8,%9}, {%0,%1,%2,%3};"
                 : "+f"(c[0]), "+f"(c[1]), "+f"(c[2]), "+f"(c[3])
                 : "r"(a0), "r"(a1), "r"(a2), "r"(a3), "r"(b0), "r"(b1));
}

// ================= f32x2 helpers (attn) =================
__device__ __forceinline__ ull dup2(float a) {
    ull r; asm("mov.b64 %0, {%1, %1};" : "=l"(r) : "f"(a)); return r;
}
__device__ __forceinline__ void fma2(ull& d, ull a, ull b) {
    asm("fma.rn.f32x2 %0, %1, %2, %0;" : "+l"(d) : "l"(a), "l"(b));
}
__device__ __forceinline__ ull add2(ull a, ull b) {
    ull r; asm("add.rn.f32x2 %0, %1, %2;" : "=l"(r) : "l"(a), "l"(b)); return r;
}
__device__ __forceinline__ ull mul2(ull a, ull b) {
    ull r; asm("mul.rn.f32x2 %0, %1, %2;" : "=l"(r) : "l"(a), "l"(b)); return r;
}
__device__ __forceinline__ float2 unpk(ull v) {
    float2 f; asm("mov.b64 {%0, %1}, %2;" : "=f"(f.x), "=f"(f.y) : "l"(v)); return f;
}

// ================= prep: weights fp32 -> bf16 hi/lo (q rows pre-scaled) =================
__global__ void k_prep(const float* __restrict__ qkvw, const float* __restrict__ projw) {
    int o = blockIdx.x, c = threadIdx.x;
    if (o < 576) {
        float v = qkvw[o * 192 + c];
        if (o < 192) v *= 0.17677669529663687f;
        __nv_bfloat16 h = __float2bfloat16(v);
        g_wqh[o * 192 + c] = h;
        g_wql[o * 192 + c] = __float2bfloat16(v - __bfloat162float(h));
    } else {
        int oo = o - 576;
        float v = projw[oo * 192 + c];
        __nv_bfloat16 h = __float2bfloat16(v);
        g_wph[oo * 192 + c] = h;
        g_wpl[oo * 192 + c] = __float2bfloat16(v - __bfloat162float(h));
    }
}

// ================= staging =================
__device__ __forceinline__ void cvt8(float4 v0, float4 v1, uint4& hi, uint4& lo) {
    __nv_bfloat162 h0 = __floats2bfloat162_rn(v0.x, v0.y);
    __nv_bfloat162 h1 = __floats2bfloat162_rn(v0.z, v0.w);
    __nv_bfloat162 h2 = __floats2bfloat162_rn(v1.x, v1.y);
    __nv_bfloat162 h3 = __floats2bfloat162_rn(v1.z, v1.w);
    float2 f0 = __bfloat1622float2(h0), f1 = __bfloat1622float2(h1);
    float2 f2 = __bfloat1622float2(h2), f3 = __bfloat1622float2(h3);
    __nv_bfloat162 l0 = __floats2bfloat162_rn(v0.x - f0.x, v0.y - f0.y);
    __nv_bfloat162 l1 = __floats2bfloat162_rn(v0.z - f1.x, v0.w - f1.y);
    __nv_bfloat162 l2 = __floats2bfloat162_rn(v1.x - f2.x, v1.y - f2.y);
    __nv_bfloat162 l3 = __floats2bfloat162_rn(v1.z - f3.x, v1.w - f3.y);
    hi = make_uint4(*(uint32_t*)&h0, *(uint32_t*)&h1, *(uint32_t*)&h2, *(uint32_t*)&h3);
    lo = make_uint4(*(uint32_t*)&l0, *(uint32_t*)&l1, *(uint32_t*)&l2, *(uint32_t*)&l3);
}

// fp32 source -> split hi/lo into smem (A tiles)
__device__ __forceinline__ void stage_rows_f32(const float* __restrict__ src, int nrows,
                                               char* dh, char* dl, int tid) {
    int groups = nrows * 24;
    for (int idx = tid; idx < groups; idx += 256) {
        int r = idx / 24, g = idx - r * 24;
        const float4* p = (const float4*)(src + (size_t)r * CDIM + g * 8);
        uint4 hi, lo;
        cvt8(p[0], p[1], hi, lo);
        uint32_t o = (uint32_t)(r * PITCH + g * 8) * 2;
        *(uint4*)(dh + o) = hi;
        *(uint4*)(dl + o) = lo;
    }
}

// pre-split bf16 source -> copy into smem (B tiles)
__device__ __forceinline__ void stage_rows_bf16(const __nv_bfloat16* __restrict__ sh,
                                                const __nv_bfloat16* __restrict__ sl,
                                                int nrows, char* dh, char* dl, int tid) {
    int groups = nrows * 24;
    for (int idx = tid; idx < groups; idx += 256) {
        int r = idx / 24, g = idx - r * 24;
        uint32_t o = (uint32_t)(r * PITCH + g * 8) * 2;
        *(uint4*)(dh + o) = *(const uint4*)(sh + (size_t)r * CDIM + g * 8);
        *(uint4*)(dl + o) = *(const uint4*)(sl + (size_t)r * CDIM + g * 8);
    }
}

// ================= warp mma core: 16x64 per warp over K=192, split-bf16 =================
__device__ __forceinline__ void mma_core(uint32_t sb, int warp, int lane, float acc[8][4]) {
#pragma unroll
    for (int nf = 0; nf < 8; ++nf)
#pragma unroll
        for (int j = 0; j < 4; ++j) acc[nf][j] = 0.0f;

    const uint32_t aoff = (uint32_t)((warp * 16 + (lane & 15)) * PITCH + (lane >> 4) * 8) * 2;
    const uint32_t boff = (uint32_t)(((lane & 7) + ((lane >> 4) << 3)) * PITCH + ((lane >> 3) & 1) * 8) * 2;
    const uint32_t aAh = sb + OFF_AH + aoff, aAl = sb + OFF_AL + aoff;
    const uint32_t aBh = sb + OFF_BH + boff, aBl = sb + OFF_BL + boff;

#pragma unroll 2
    for (int kc = 0; kc < 12; ++kc) {
        uint32_t ko = kc * 32;
        uint32_t ah[4], al[4], bh[8][2], bl[8][2];
        ldsm4(ah[0], ah[1], ah[2], ah[3], aAh + ko);
        ldsm4(al[0], al[1], al[2], al[3], aAl + ko);
#pragma unroll
        for (int np = 0; np < 4; ++np) {
            ldsm4(bh[2 * np][0], bh[2 * np][1], bh[2 * np + 1][0], bh[2 * np + 1][1],
                  aBh + np * (16 * PITCH * 2) + ko);
            ldsm4(bl[2 * np][0], bl[2 * np][1], bl[2 * np + 1][0], bl[2 * np + 1][1],
                  aBl + np * (16 * PITCH * 2) + ko);
        }
#pragma unroll
        for (int nf = 0; nf < 8; ++nf) {
            mma16816(acc[nf], ah[0], ah[1], ah[2], ah[3], bh[nf][0], bh[nf][1]);
            mma16816(acc[nf], ah[0], ah[1], ah[2], ah[3], bl[nf][0], bl[nf][1]);
            mma16816(acc[nf], al[0], al[1], al[2], al[3], bh[nf][0], bh[nf][1]);
        }
    }
}

// ================= K1: QKV GEMM + window scatter =================
// grid(2048): 128 pixel rows per CTA; 256 thr (8 warps x 16 rows); loop 9 N-tiles.
__global__ __launch_bounds__(256) void k_qkv(const float* __restrict__ x) {
    extern __shared__ char smem[];
    uint32_t sb = smem_to_u32(smem);
    int tid = threadIdx.x, mt = blockIdx.x;
    int warp = tid >> 5, lane = tid & 31;

    stage_rows_f32(x + (size_t)mt * 128 * CDIM, 128, smem + OFF_AH, smem + OFF_AL, tid);

    for (int nt = 0; nt < 9; ++nt) {
        stage_rows_bf16(g_wqh + (size_t)nt * 64 * CDIM, g_wql + (size_t)nt * 64 * CDIM,
                        64, smem + OFF_BH, smem + OFF_BL, tid);
        __syncthreads();

        float acc[8][4];
        mma_core(sb, warp, lane, acc);

        int which = nt / 3;
        int rem0 = (nt - which * 3) * 64;
        size_t plane = (size_t)which * NW * NHD * 2048;
#pragma unroll
        for (int half = 0; half < 2; ++half) {
            int p = mt * 128 + warp * 16 + (lane >> 2) + half * 8;
            int b = p >> 16, y = (p >> 8) & 255, xc = p & 255;
            int w = (b << 10) | ((y >> 3) << 5) | (xc >> 3);
            int t = ((y & 7) << 3) | (xc & 7);
            size_t base = plane + ((size_t)w * NHD) * 2048 + t * 32;
#pragma unroll
            for (int nf = 0; nf < 8; ++nf) {
                int rem = rem0 + nf * 8 + (lane & 3) * 2;
                int h = rem >> 5, d = rem & 31;
                *(float2*)(g_qkv + base + (size_t)h * 2048 + d) =
                    make_float2(acc[nf][half * 2], acc[nf][half * 2 + 1]);
            }
        }
        __syncthreads();
    }
}

// ================= K2: windowed attention (VERBATIM passing version) =================
__global__ __launch_bounds__(32) void k_attn(const float* __restrict__ rpb) {
    __shared__ float ks[2048], vs[2048], bias_s[240];
    int h = blockIdx.x, w = blockIdx.y, lane = threadIdx.x;
    size_t base = ((size_t)(w * NHD + h)) << 11;
    const size_t plane = (size_t)NW * NHD * 2048;
    const float4* kp4 = (const float4*)(g_qkv + plane + base);
    const float4* vp4 = (const float4*)(g_qkv + 2 * plane + base);
#pragma unroll
    for (int u = 0; u < 16; ++u) {
        ((float4*)ks)[(u << 5) + lane] = kp4[(u << 5) + lane];
        ((float4*)vs)[(u << 5) + lane] = vp4[(u << 5) + lane];
    }
    for (int i = lane; i < 225; i += 32) bias_s[i] = rpb[i * NHD + h];
    __syncthreads();

    int q0 = lane << 1, q1 = q0 + 1;
    ull qr0[16], qr1[16];
    const ull* qp = (const ull*)(g_qkv + base + (size_t)q0 * HD);
#pragma unroll
    for (int i = 0; i < 16; ++i) { qr0[i] = qp[i]; qr1[i] = qp[16 + i]; }

    int q0i = q0 >> 3, q0j = q0 & 7;
    int q1i = q1 >> 3, q1j = q1 & 7;
    ull acc0[16], acc1[16];
#pragma unroll
    for (int i = 0; i < 16; ++i) { acc0[i] = 0ull; acc1[i] = 0ull; }
    float sum0 = 0.0f, sum1 = 0.0f;

#pragma unroll 4
    for (int kk = 0; kk < 64; ++kk) {
        const ull* kr = (const ull*)(ks + (kk << 5));
        ull e00 = 0ull, e01 = 0ull, e10 = 0ull, e11 = 0ull;
#pragma unroll
        for (int i = 0; i < 8; ++i) {
            ull k0 = kr[2 * i], k1 = kr[2 * i + 1];
            fma2(e00, qr0[2 * i], k0);
            fma2(e01, qr0[2 * i + 1], k1);
            fma2(e10, qr1[2 * i], k0);
            fma2(e11, qr1[2 * i + 1], k1);
        }
        int ki = kk >> 3, kj = kk & 7;
        int bidx = (7 - ki) * 15 + (7 - kj);
        float2 f0 = unpk(add2(e00, e01));
        float2 f1 = unpk(add2(e10, e11));
        float p0 = __expf(f0.x + f0.y + bias_s[bidx + q0i * 15 + q0j]);
        float p1 = __expf(f1.x + f1.y + bias_s[bidx + q1i * 15 + q1j]);
        sum0 += p0; sum1 += p1;
        ull pv0 = dup2(p0), pv1 = dup2(p1);
        const ull* vr = (const ull*)(vs + (kk << 5));
#pragma unroll
        for (int i = 0; i < 16; ++i) {
            ull vv = vr[i];
            fma2(acc0[i], pv0, vv);
            fma2(acc1[i], pv1, vv);
        }
    }

    ull inv0 = dup2(1.0f / sum0), inv1 = dup2(1.0f / sum1);
    ull* op0 = (ull*)(g_att + ((size_t)w * WS2 + q0) * CDIM + h * HD);
    ull* op1 = (ull*)(g_att + ((size_t)w * WS2 + q1) * CDIM + h * HD);
#pragma unroll
    for (int i = 0; i < 16; ++i) {
        op0[i] = mul2(acc0[i], inv0);
        op1[i] = mul2(acc1[i], inv1);
    }
}

// ================= K3: proj GEMM + bias + pixel scatter =================
// grid(2048): 128 g_att rows per CTA; 256 thr; loop 3 N-tiles.
__global__ __launch_bounds__(256) void k_proj(const float* __restrict__ pb,
                                              float* __restrict__ out) {
    extern __shared__ char smem[];
    uint32_t sb = smem_to_u32(smem);
    int tid = threadIdx.x, mt = blockIdx.x;
    int warp = tid >> 5, lane = tid & 31;

    stage_rows_f32(g_att + (size_t)mt * 128 * CDIM, 128, smem + OFF_AH, smem + OFF_AL, tid);

    for (int nt = 0; nt < 3; ++nt) {
        stage_rows_bf16(g_wph + (size_t)nt * 64 * CDIM, g_wpl + (size_t)nt * 64 * CDIM,
                        64, smem + OFF_BH, smem + OFF_BL, tid);
        __syncthreads();

        float acc[8][4];
        mma_core(sb, warp, lane, acc);

#pragma unroll
        for (int half = 0; half < 2; ++half) {
            int p = mt * 128 + warp * 16 + (lane >> 2) + half * 8;
            int w = p >> 6, t = p & 63;
            int b = w >> 10, wh = (w >> 5) & 31, ww = w & 31;
            int ri = t >> 3, ci = t & 7;
            size_t pix = (size_t)((b << 8) + (wh << 3) + ri) * 256 + (ww << 3) + ci;
            float* o = out + pix * CDIM;
#pragma unroll
            for (int nf = 0; nf < 8; ++nf) {
                int oc = nt * 64 + nf * 8 + (lane & 3) * 2;
                float2 bias = *(const float2*)(pb + oc);
                *(float2*)(o + oc) = make_float2(acc[nf][half * 2] + bias.x,
                                                 acc[nf][half * 2 + 1] + bias.y);
            }
        }
        __syncthreads();
    }
}

// ================= launch =================
extern "C" void kernel_launch(void* const* d_in, const int* in_sizes, int n_in,
                              void* d_out, int out_size) {
    const float* x     = (const float*)d_in[0];
    const float* qkvw  = (const float*)d_in[1];
    const float* projw = (const float*)d_in[2];
    const float* pb    = (const float*)d_in[3];
    const float* rpb   = (const float*)d_in[4];
    (void)in_sizes; (void)n_in; (void)out_size;

    cudaFuncSetAttribute(k_qkv,  cudaFuncAttributeMaxDynamicSharedMemorySize, GEMM_SMEM);
    cudaFuncSetAttribute(k_proj, cudaFuncAttributeMaxDynamicSharedMemorySize, GEMM_SMEM);

    k_prep<<<768, 192>>>(qkvw, projw);
    k_qkv <<<2048, 256, GEMM_SMEM>>>(x);
    k_attn<<<dim3(NHD, NW), 32>>>(rpb);
    k_proj<<<2048, 256, GEMM_SMEM>>>(pb, (float*)d_out);
}

// round 13
// speedup vs baseline: 1.0832x; 1.0832x over previous
#include <cuda_runtime.h>
#include <cuda_bf16.h>
#include <cstdint>

typedef unsigned long long ull;

#define NW   4096
#define NHD  6
#define HD   32
#define CDIM 192
#define WS2  64

// smem layout (bf16, row pitch 200 elems => 400B rows, ldmatrix conflict-free)
#define PITCH  200
#define OFF_AH 0
#define OFF_AL 51200
#define OFF_B0 102400            // buf0: hi @ +0, lo @ +25600
#define OFF_B1 153600            // buf1: hi @ +0, lo @ +25600
#define GEMM_SMEM 204800

// ---- scratch ----
__device__ float g_qkv[(size_t)3 * NW * NHD * WS2 * HD];   // [which][w][h][t][d]
__device__ float g_att[(size_t)NW * WS2 * CDIM];           // [w][t][h*32+d]
__device__ __nv_bfloat16 g_wqh[576 * 192], g_wql[576 * 192];  // qkv weights hi/lo (q pre-scaled)
__device__ __nv_bfloat16 g_wph[192 * 192], g_wpl[192 * 192];  // proj weights hi/lo

// ================= helpers =================
__device__ __forceinline__ uint32_t smem_to_u32(const void* p) {
    uint32_t a;
    asm("{ .reg .u64 t; cvta.to.shared.u64 t, %1; cvt.u32.u64 %0, t; }" : "=r"(a) : "l"(p));
    return a;
}
__device__ __forceinline__ void ldsm4(uint32_t& r0, uint32_t& r1, uint32_t& r2, uint32_t& r3,
                                      uint32_t addr) {
    asm volatile("ldmatrix.sync.aligned.m8n8.x4.shared.b16 {%0,%1,%2,%3}, [%4];"
                 : "=r"(r0), "=r"(r1), "=r"(r2), "=r"(r3) : "r"(addr));
}
__device__ __forceinline__ void mma16816(float* c, uint32_t a0, uint32_t a1, uint32_t a2,
                                         uint32_t a3, uint32_t b0, uint32_t b1) {
    asm volatile("mma.sync.aligned.m16n8k16.row.col.f32.bf16.bf16.f32 "
                 "{%0,%1,%2,%3}, {%4,%5,%6,%7}, {%8,%9}, {%0,%1,%2,%3};"
                 : "+f"(c[0]), "+f"(c[1]), "+f"(c[2]), "+f"(c[3])
                 : "r"(a0), "r"(a1), "r"(a2), "r"(a3), "r"(b0), "r"(b1));
}
#define CP_ASYNC16(dst, src) \
    asm volatile("cp.async.cg.shared.global [%0], [%1], 16;" :: "r"(dst), "l"(src) : "memory")
#define CP_COMMIT() asm volatile("cp.async.commit_group;" ::: "memory")
#define CP_WAIT0()  asm volatile("cp.async.wait_group 0;" ::: "memory")

// ================= f32x2 helpers (attn) =================
__device__ __forceinline__ ull dup2(float a) {
    ull r; asm("mov.b64 %0, {%1, %1};" : "=l"(r) : "f"(a)); return r;
}
__device__ __forceinline__ void fma2(ull& d, ull a, ull b) {
    asm("fma.rn.f32x2 %0, %1, %2, %0;" : "+l"(d) : "l"(a), "l"(b));
}
__device__ __forceinline__ ull add2(ull a, ull b) {
    ull r; asm("add.rn.f32x2 %0, %1, %2;" : "=l"(r) : "l"(a), "l"(b)); return r;
}
__device__ __forceinline__ ull mul2(ull a, ull b) {
    ull r; asm("mul.rn.f32x2 %0, %1, %2;" : "=l"(r) : "l"(a), "l"(b)); return r;
}
__device__ __forceinline__ float2 unpk(ull v) {
    float2 f; asm("mov.b64 {%0, %1}, %2;" : "=f"(f.x), "=f"(f.y) : "l"(v)); return f;
}

// ================= prep: weights fp32 -> bf16 hi/lo (q rows pre-scaled) =================
__global__ void k_prep(const float* __restrict__ qkvw, const float* __restrict__ projw) {
    int o = blockIdx.x, c = threadIdx.x;
    if (o < 576) {
        float v = qkvw[o * 192 + c];
        if (o < 192) v *= 0.17677669529663687f;
        __nv_bfloat16 h = __float2bfloat16(v);
        g_wqh[o * 192 + c] = h;
        g_wql[o * 192 + c] = __float2bfloat16(v - __bfloat162float(h));
    } else {
        int oo = o - 576;
        float v = projw[oo * 192 + c];
        __nv_bfloat16 h = __float2bfloat16(v);
        g_wph[oo * 192 + c] = h;
        g_wpl[oo * 192 + c] = __float2bfloat16(v - __bfloat162float(h));
    }
}

// ================= A staging: fp32 -> bf16 hi/lo split =================
__device__ __forceinline__ void cvt8(float4 v0, float4 v1, uint4& hi, uint4& lo) {
    __nv_bfloat162 h0 = __floats2bfloat162_rn(v0.x, v0.y);
    __nv_bfloat162 h1 = __floats2bfloat162_rn(v0.z, v0.w);
    __nv_bfloat162 h2 = __floats2bfloat162_rn(v1.x, v1.y);
    __nv_bfloat162 h3 = __floats2bfloat162_rn(v1.z, v1.w);
    float2 f0 = __bfloat1622float2(h0), f1 = __bfloat1622float2(h1);
    float2 f2 = __bfloat1622float2(h2), f3 = __bfloat1622float2(h3);
    __nv_bfloat162 l0 = __floats2bfloat162_rn(v0.x - f0.x, v0.y - f0.y);
    __nv_bfloat162 l1 = __floats2bfloat162_rn(v0.z - f1.x, v0.w - f1.y);
    __nv_bfloat162 l2 = __floats2bfloat162_rn(v1.x - f2.x, v1.y - f2.y);
    __nv_bfloat162 l3 = __floats2bfloat162_rn(v1.z - f3.x, v1.w - f3.y);
    hi = make_uint4(*(uint32_t*)&h0, *(uint32_t*)&h1, *(uint32_t*)&h2, *(uint32_t*)&h3);
    lo = make_uint4(*(uint32_t*)&l0, *(uint32_t*)&l1, *(uint32_t*)&l2, *(uint32_t*)&l3);
}

__device__ __forceinline__ void stage_rows_f32(const float* __restrict__ src, int nrows,
                                               char* dh, char* dl, int tid) {
    int groups = nrows * 24;
    for (int idx = tid; idx < groups; idx += 256) {
        int r = idx / 24, g = idx - r * 24;
        const float4* p = (const float4*)(src + (size_t)r * CDIM + g * 8);
        uint4 hi, lo;
        cvt8(p[0], p[1], hi, lo);
        uint32_t o = (uint32_t)(r * PITCH + g * 8) * 2;
        *(uint4*)(dh + o) = hi;
        *(uint4*)(dl + o) = lo;
    }
}

// B staging via cp.async (pre-split bf16 hi/lo, 64 rows)
__device__ __forceinline__ void stage_b_async(const __nv_bfloat16* __restrict__ sh,
                                              const __nv_bfloat16* __restrict__ sl,
                                              uint32_t dbuf, int tid) {
    for (int idx = tid; idx < 1536; idx += 256) {
        int r = idx / 24, g = idx - r * 24;
        uint32_t o = (uint32_t)(r * PITCH + g * 8) * 2;
        CP_ASYNC16(dbuf + o, sh + (size_t)r * CDIM + g * 8);
        CP_ASYNC16(dbuf + 25600 + o, sl + (size_t)r * CDIM + g * 8);
    }
}

// ================= warp mma core: 16x64 per warp over K=192, split-bf16 =================
__device__ __forceinline__ void mma_core(uint32_t sb, uint32_t bbuf, int warp, int lane,
                                         float acc[8][4]) {
#pragma unroll
    for (int nf = 0; nf < 8; ++nf)
#pragma unroll
        for (int j = 0; j < 4; ++j) acc[nf][j] = 0.0f;

    const uint32_t aoff = (uint32_t)((warp * 16 + (lane & 15)) * PITCH + (lane >> 4) * 8) * 2;
    const uint32_t boff = (uint32_t)(((lane & 7) + ((lane >> 4) << 3)) * PITCH + ((lane >> 3) & 1) * 8) * 2;
    const uint32_t aAh = sb + OFF_AH + aoff, aAl = sb + OFF_AL + aoff;
    const uint32_t aBh = sb + bbuf + boff,   aBl = sb + bbuf + 25600 + boff;

#pragma unroll 2
    for (int kc = 0; kc < 12; ++kc) {
        uint32_t ko = kc * 32;
        uint32_t ah[4], al[4], bh[8][2], bl[8][2];
        ldsm4(ah[0], ah[1], ah[2], ah[3], aAh + ko);
        ldsm4(al[0], al[1], al[2], al[3], aAl + ko);
#pragma unroll
        for (int np = 0; np < 4; ++np) {
            ldsm4(bh[2 * np][0], bh[2 * np][1], bh[2 * np + 1][0], bh[2 * np + 1][1],
                  aBh + np * (16 * PITCH * 2) + ko);
            ldsm4(bl[2 * np][0], bl[2 * np][1], bl[2 * np + 1][0], bl[2 * np + 1][1],
                  aBl + np * (16 * PITCH * 2) + ko);
        }
#pragma unroll
        for (int nf = 0; nf < 8; ++nf) {
            mma16816(acc[nf], ah[0], ah[1], ah[2], ah[3], bh[nf][0], bh[nf][1]);
            mma16816(acc[nf], ah[0], ah[1], ah[2], ah[3], bl[nf][0], bl[nf][1]);
            mma16816(acc[nf], al[0], al[1], al[2], al[3], bh[nf][0], bh[nf][1]);
        }
    }
}

// ================= K1: QKV GEMM + window scatter =================
// grid(2048): 128 pixel rows per CTA; 256 thr; 9 N-tiles, cp.async double-buffered B.
__global__ __launch_bounds__(256) void k_qkv(const float* __restrict__ x) {
    extern __shared__ char smem[];
    uint32_t sb = smem_to_u32(smem);
    int tid = threadIdx.x, mt = blockIdx.x;
    int warp = tid >> 5, lane = tid & 31;

    // prefetch B0 while converting A
    stage_b_async(g_wqh, g_wql, sb + OFF_B0, tid);
    CP_COMMIT();
    stage_rows_f32(x + (size_t)mt * 128 * CDIM, 128, smem + OFF_AH, smem + OFF_AL, tid);
    CP_WAIT0();
    __syncthreads();

    for (int nt = 0; nt < 9; ++nt) {
        uint32_t cur = (nt & 1) ? OFF_B1 : OFF_B0;
        if (nt + 1 < 9) {
            uint32_t nxt = (nt & 1) ? OFF_B0 : OFF_B1;
            stage_b_async(g_wqh + (size_t)(nt + 1) * 64 * CDIM,
                          g_wql + (size_t)(nt + 1) * 64 * CDIM, sb + nxt, tid);
            CP_COMMIT();
        }

        float acc[8][4];
        mma_core(sb, cur, warp, lane, acc);

        int which = nt / 3;
        int rem0 = (nt - which * 3) * 64;
        size_t plane = (size_t)which * NW * NHD * 2048;
#pragma unroll
        for (int half = 0; half < 2; ++half) {
            int p = mt * 128 + warp * 16 + (lane >> 2) + half * 8;
            int b = p >> 16, y = (p >> 8) & 255, xc = p & 255;
            int w = (b << 10) | ((y >> 3) << 5) | (xc >> 3);
            int t = ((y & 7) << 3) | (xc & 7);
            size_t base = plane + ((size_t)w * NHD) * 2048 + t * 32;
#pragma unroll
            for (int nf = 0; nf < 8; ++nf) {
                int rem = rem0 + nf * 8 + (lane & 3) * 2;
                int h = rem >> 5, d = rem & 31;
                *(float2*)(g_qkv + base + (size_t)h * 2048 + d) =
                    make_float2(acc[nf][half * 2], acc[nf][half * 2 + 1]);
            }
        }
        if (nt + 1 < 9) CP_WAIT0();
        __syncthreads();
    }
}

// ================= K2: windowed attention (VERBATIM passing version) =================
__global__ __launch_bounds__(32) void k_attn(const float* __restrict__ rpb) {
    __shared__ float ks[2048], vs[2048], bias_s[240];
    int h = blockIdx.x, w = blockIdx.y, lane = threadIdx.x;
    size_t base = ((size_t)(w * NHD + h)) << 11;
    const size_t plane = (size_t)NW * NHD * 2048;
    const float4* kp4 = (const float4*)(g_qkv + plane + base);
    const float4* vp4 = (const float4*)(g_qkv + 2 * plane + base);
#pragma unroll
    for (int u = 0; u < 16; ++u) {
        ((float4*)ks)[(u << 5) + lane] = kp4[(u << 5) + lane];
        ((float4*)vs)[(u << 5) + lane] = vp4[(u << 5) + lane];
    }
    for (int i = lane; i < 225; i += 32) bias_s[i] = rpb[i * NHD + h];
    __syncthreads();

    int q0 = lane << 1, q1 = q0 + 1;
    ull qr0[16], qr1[16];
    const ull* qp = (const ull*)(g_qkv + base + (size_t)q0 * HD);
#pragma unroll
    for (int i = 0; i < 16; ++i) { qr0[i] = qp[i]; qr1[i] = qp[16 + i]; }

    int q0i = q0 >> 3, q0j = q0 & 7;
    int q1i = q1 >> 3, q1j = q1 & 7;
    ull acc0[16], acc1[16];
#pragma unroll
    for (int i = 0; i < 16; ++i) { acc0[i] = 0ull; acc1[i] = 0ull; }
    float sum0 = 0.0f, sum1 = 0.0f;

#pragma unroll 4
    for (int kk = 0; kk < 64; ++kk) {
        const ull* kr = (const ull*)(ks + (kk << 5));
        ull e00 = 0ull, e01 = 0ull, e10 = 0ull, e11 = 0ull;
#pragma unroll
        for (int i = 0; i < 8; ++i) {
            ull k0 = kr[2 * i], k1 = kr[2 * i + 1];
            fma2(e00, qr0[2 * i], k0);
            fma2(e01, qr0[2 * i + 1], k1);
            fma2(e10, qr1[2 * i], k0);
            fma2(e11, qr1[2 * i + 1], k1);
        }
        int ki = kk >> 3, kj = kk & 7;
        int bidx = (7 - ki) * 15 + (7 - kj);
        float2 f0 = unpk(add2(e00, e01));
        float2 f1 = unpk(add2(e10, e11));
        float p0 = __expf(f0.x + f0.y + bias_s[bidx + q0i * 15 + q0j]);
        float p1 = __expf(f1.x + f1.y + bias_s[bidx + q1i * 15 + q1j]);
        sum0 += p0; sum1 += p1;
        ull pv0 = dup2(p0), pv1 = dup2(p1);
        const ull* vr = (const ull*)(vs + (kk << 5));
#pragma unroll
        for (int i = 0; i < 16; ++i) {
            ull vv = vr[i];
            fma2(acc0[i], pv0, vv);
            fma2(acc1[i], pv1, vv);
        }
    }

    ull inv0 = dup2(1.0f / sum0), inv1 = dup2(1.0f / sum1);
    ull* op0 = (ull*)(g_att + ((size_t)w * WS2 + q0) * CDIM + h * HD);
    ull* op1 = (ull*)(g_att + ((size_t)w * WS2 + q1) * CDIM + h * HD);
#pragma unroll
    for (int i = 0; i < 16; ++i) {
        op0[i] = mul2(acc0[i], inv0);
        op1[i] = mul2(acc1[i], inv1);
    }
}

// ================= K3: proj GEMM + bias + pixel scatter =================
// grid(2048): 128 g_att rows per CTA; 256 thr; 3 N-tiles, cp.async double-buffered B.
__global__ __launch_bounds__(256) void k_proj(const float* __restrict__ pb,
                                              float* __restrict__ out) {
    extern __shared__ char smem[];
    uint32_t sb = smem_to_u32(smem);
    int tid = threadIdx.x, mt = blockIdx.x;
    int warp = tid >> 5, lane = tid & 31;

    stage_b_async(g_wph, g_wpl, sb + OFF_B0, tid);
    CP_COMMIT();
    stage_rows_f32(g_att + (size_t)mt * 128 * CDIM, 128, smem + OFF_AH, smem + OFF_AL, tid);
    CP_WAIT0();
    __syncthreads();

    for (int nt = 0; nt < 3; ++nt) {
        uint32_t cur = (nt & 1) ? OFF_B1 : OFF_B0;
        if (nt + 1 < 3) {
            uint32_t nxt = (nt & 1) ? OFF_B0 : OFF_B1;
            stage_b_async(g_wph + (size_t)(nt + 1) * 64 * CDIM,
                          g_wpl + (size_t)(nt + 1) * 64 * CDIM, sb + nxt, tid);
            CP_COMMIT();
        }

        float acc[8][4];
        mma_core(sb, cur, warp, lane, acc);

#pragma unroll
        for (int half = 0; half < 2; ++half) {
            int p = mt * 128 + warp * 16 + (lane >> 2) + half * 8;
            int w = p >> 6, t = p & 63;
            int b = w >> 10, wh = (w >> 5) & 31, ww = w & 31;
            int ri = t >> 3, ci = t & 7;
            size_t pix = (size_t)((b << 8) + (wh << 3) + ri) * 256 + (ww << 3) + ci;
            float* o = out + pix * CDIM;
#pragma unroll
            for (int nf = 0; nf < 8; ++nf) {
                int oc = nt * 64 + nf * 8 + (lane & 3) * 2;
                float2 bias = *(const float2*)(pb + oc);
                *(float2*)(o + oc) = make_float2(acc[nf][half * 2] + bias.x,
                                                 acc[nf][half * 2 + 1] + bias.y);
            }
        }
        if (nt + 1 < 3) CP_WAIT0();
        __syncthreads();
    }
}

// ================= launch =================
extern "C" void kernel_launch(void* const* d_in, const int* in_sizes, int n_in,
                              void* d_out, int out_size) {
    const float* x     = (const float*)d_in[0];
    const float* qkvw  = (const float*)d_in[1];
    const float* projw = (const float*)d_in[2];
    const float* pb    = (const float*)d_in[3];
    const float* rpb   = (const float*)d_in[4];
    (void)in_sizes; (void)n_in; (void)out_size;

    cudaFuncSetAttribute(k_qkv,  cudaFuncAttributeMaxDynamicSharedMemorySize, GEMM_SMEM);
    cudaFuncSetAttribute(k_proj, cudaFuncAttributeMaxDynamicSharedMemorySize, GEMM_SMEM);

    k_prep<<<768, 192>>>(qkvw, projw);
    k_qkv <<<2048, 256, GEMM_SMEM>>>(x);
    k_attn<<<dim3(NHD, NW), 32>>>(rpb);
    k_proj<<<2048, 256, GEMM_SMEM>>>(pb, (float*)d_out);
}

// round 14
// speedup vs baseline: 1.2422x; 1.1467x over previous
#include <cuda_runtime.h>
#include <cuda_bf16.h>
#include <cstdint>

typedef unsigned long long ull;

#define NW   4096
#define NHD  6
#define HD   32
#define CDIM 192
#define WS2  64

// smem layout (bf16, row pitch 200 elems => 400B rows, ldmatrix conflict-free)
#define PITCH  200
#define OFF_AH 0
#define OFF_AL 51200
#define OFF_B0 102400            // buf: hi @ +0, lo @ +25600
#define OFF_B1 153600
#define GEMM_SMEM 204800
#define NTHR 512

// ---- scratch ----
__device__ float g_qkv[(size_t)3 * NW * NHD * WS2 * HD];        // [which][w][h][t][d]
__device__ __nv_bfloat16 g_ath[(size_t)NW * WS2 * CDIM];        // attn out hi  [w*64+t][c]
__device__ __nv_bfloat16 g_atl[(size_t)NW * WS2 * CDIM];        // attn out lo
__device__ __nv_bfloat16 g_wqh[576 * 192], g_wql[576 * 192];    // qkv weights hi/lo (q pre-scaled)
__device__ __nv_bfloat16 g_wph[192 * 192], g_wpl[192 * 192];    // proj weights hi/lo

// ================= helpers =================
__device__ __forceinline__ uint32_t smem_to_u32(const void* p) {
    uint32_t a;
    asm("{ .reg .u64 t; cvta.to.shared.u64 t, %1; cvt.u32.u64 %0, t; }" : "=r"(a) : "l"(p));
    return a;
}
__device__ __forceinline__ void ldsm4(uint32_t& r0, uint32_t& r1, uint32_t& r2, uint32_t& r3,
                                      uint32_t addr) {
    asm volatile("ldmatrix.sync.aligned.m8n8.x4.shared.b16 {%0,%1,%2,%3}, [%4];"
                 : "=r"(r0), "=r"(r1), "=r"(r2), "=r"(r3) : "r"(addr));
}
__device__ __forceinline__ void mma16816(float* c, uint32_t a0, uint32_t a1, uint32_t a2,
                                         uint32_t a3, uint32_t b0, uint32_t b1) {
    asm volatile("mma.sync.aligned.m16n8k16.row.col.f32.bf16.bf16.f32 "
                 "{%0,%1,%2,%3}, {%4,%5,%6,%7}, {%8,%9}, {%0,%1,%2,%3};"
                 : "+f"(c[0]), "+f"(c[1]), "+f"(c[2]), "+f"(c[3])
                 : "r"(a0), "r"(a1), "r"(a2), "r"(a3), "r"(b0), "r"(b1));
}
#define CP_ASYNC16(dst, src) \
    asm volatile("cp.async.cg.shared.global [%0], [%1], 16;" :: "r"(dst), "l"(src) : "memory")
#define CP_COMMIT() asm volatile("cp.async.commit_group;" ::: "memory")
#define CP_WAIT0()  asm volatile("cp.async.wait_group 0;" ::: "memory")

// ================= f32x2 helpers (attn) =================
__device__ __forceinline__ ull dup2(float a) {
    ull r; asm("mov.b64 %0, {%1, %1};" : "=l"(r) : "f"(a)); return r;
}
__device__ __forceinline__ void fma2(ull& d, ull a, ull b) {
    asm("fma.rn.f32x2 %0, %1, %2, %0;" : "+l"(d) : "l"(a), "l"(b));
}
__device__ __forceinline__ ull add2(ull a, ull b) {
    ull r; asm("add.rn.f32x2 %0, %1, %2;" : "=l"(r) : "l"(a), "l"(b)); return r;
}
__device__ __forceinline__ ull mul2(ull a, ull b) {
    ull r; asm("mul.rn.f32x2 %0, %1, %2;" : "=l"(r) : "l"(a), "l"(b)); return r;
}
__device__ __forceinline__ float2 unpk(ull v) {
    float2 f; asm("mov.b64 {%0, %1}, %2;" : "=f"(f.x), "=f"(f.y) : "l"(v)); return f;
}

// ================= prep: weights fp32 -> bf16 hi/lo (q rows pre-scaled) =================
__global__ void k_prep(const float* __restrict__ qkvw, const float* __restrict__ projw) {
    int o = blockIdx.x, c = threadIdx.x;
    if (o < 576) {
        float v = qkvw[o * 192 + c];
        if (o < 192) v *= 0.17677669529663687f;
        __nv_bfloat16 h = __float2bfloat16(v);
        g_wqh[o * 192 + c] = h;
        g_wql[o * 192 + c] = __float2bfloat16(v - __bfloat162float(h));
    } else {
        int oo = o - 576;
        float v = projw[oo * 192 + c];
        __nv_bfloat16 h = __float2bfloat16(v);
        g_wph[oo * 192 + c] = h;
        g_wpl[oo * 192 + c] = __float2bfloat16(v - __bfloat162float(h));
    }
}

// ================= staging =================
__device__ __forceinline__ void cvt8(float4 v0, float4 v1, uint4& hi, uint4& lo) {
    __nv_bfloat162 h0 = __floats2bfloat162_rn(v0.x, v0.y);
    __nv_bfloat162 h1 = __floats2bfloat162_rn(v0.z, v0.w);
    __nv_bfloat162 h2 = __floats2bfloat162_rn(v1.x, v1.y);
    __nv_bfloat162 h3 = __floats2bfloat162_rn(v1.z, v1.w);
    float2 f0 = __bfloat1622float2(h0), f1 = __bfloat1622float2(h1);
    float2 f2 = __bfloat1622float2(h2), f3 = __bfloat1622float2(h3);
    __nv_bfloat162 l0 = __floats2bfloat162_rn(v0.x - f0.x, v0.y - f0.y);
    __nv_bfloat162 l1 = __floats2bfloat162_rn(v0.z - f1.x, v0.w - f1.y);
    __nv_bfloat162 l2 = __floats2bfloat162_rn(v1.x - f2.x, v1.y - f2.y);
    __nv_bfloat162 l3 = __floats2bfloat162_rn(v1.z - f3.x, v1.w - f3.y);
    hi = make_uint4(*(uint32_t*)&h0, *(uint32_t*)&h1, *(uint32_t*)&h2, *(uint32_t*)&h3);
    lo = make_uint4(*(uint32_t*)&l0, *(uint32_t*)&l1, *(uint32_t*)&l2, *(uint32_t*)&l3);
}

// fp32 source -> split hi/lo into smem (k_qkv A tile)
__device__ __forceinline__ void stage_rows_f32(const float* __restrict__ src, int nrows,
                                               char* dh, char* dl, int tid) {
    int groups = nrows * 24;
    for (int idx = tid; idx < groups; idx += NTHR) {
        int r = idx / 24, g = idx - r * 24;
        const float4* p = (const float4*)(src + (size_t)r * CDIM + g * 8);
        uint4 hi, lo;
        cvt8(p[0], p[1], hi, lo);
        uint32_t o = (uint32_t)(r * PITCH + g * 8) * 2;
        *(uint4*)(dh + o) = hi;
        *(uint4*)(dl + o) = lo;
    }
}

// pre-split bf16 hi/lo -> smem via cp.async
__device__ __forceinline__ void stage_async(const __nv_bfloat16* __restrict__ sh,
                                            const __nv_bfloat16* __restrict__ sl,
                                            uint32_t dbuf, uint32_t lo_delta,
                                            int nrows, int tid) {
    int groups = nrows * 24;
    for (int idx = tid; idx < groups; idx += NTHR) {
        int r = idx / 24, g = idx - r * 24;
        uint32_t o = (uint32_t)(r * PITCH + g * 8) * 2;
        CP_ASYNC16(dbuf + o, sh + (size_t)r * CDIM + g * 8);
        CP_ASYNC16(dbuf + lo_delta + o, sl + (size_t)r * CDIM + g * 8);
    }
}

// ================= warp mma core: 16x32 per warp over K=192, split-bf16 =================
// 16 warps: mslice = warp>>1 (0..7), nslice = warp&1 (0..1).
__device__ __forceinline__ void mma_core(uint32_t sb, uint32_t bbuf, int mslice, int nslice,
                                         int lane, float acc[4][4]) {
#pragma unroll
    for (int nf = 0; nf < 4; ++nf)
#pragma unroll
        for (int j = 0; j < 4; ++j) acc[nf][j] = 0.0f;

    const uint32_t aoff = (uint32_t)((mslice * 16 + (lane & 15)) * PITCH + (lane >> 4) * 8) * 2;
    const uint32_t boff = (uint32_t)((nslice * 32 + (lane & 7) + ((lane >> 4) << 3)) * PITCH
                                     + ((lane >> 3) & 1) * 8) * 2;
    const uint32_t aAh = sb + OFF_AH + aoff, aAl = sb + OFF_AL + aoff;
    const uint32_t aBh = sb + bbuf + boff,   aBl = sb + bbuf + 25600 + boff;

#pragma unroll 2
    for (int kc = 0; kc < 12; ++kc) {
        uint32_t ko = kc * 32;
        uint32_t ah[4], al[4], bh[4][2], bl[4][2];
        ldsm4(ah[0], ah[1], ah[2], ah[3], aAh + ko);
        ldsm4(al[0], al[1], al[2], al[3], aAl + ko);
#pragma unroll
        for (int np = 0; np < 2; ++np) {
            ldsm4(bh[2 * np][0], bh[2 * np][1], bh[2 * np + 1][0], bh[2 * np + 1][1],
                  aBh + np * (16 * PITCH * 2) + ko);
            ldsm4(bl[2 * np][0], bl[2 * np][1], bl[2 * np + 1][0], bl[2 * np + 1][1],
                  aBl + np * (16 * PITCH * 2) + ko);
        }
#pragma unroll
        for (int nf = 0; nf < 4; ++nf) {
            mma16816(acc[nf], ah[0], ah[1], ah[2], ah[3], bh[nf][0], bh[nf][1]);
            mma16816(acc[nf], ah[0], ah[1], ah[2], ah[3], bl[nf][0], bl[nf][1]);
            mma16816(acc[nf], al[0], al[1], al[2], al[3], bh[nf][0], bh[nf][1]);
        }
    }
}

// ================= K1: QKV GEMM + window scatter =================
// grid(2048): 128 pixel rows per CTA; 512 thr; 9 N-tiles, cp.async double-buffered B.
__global__ __launch_bounds__(NTHR) void k_qkv(const float* __restrict__ x) {
    extern __shared__ char smem[];
    uint32_t sb = smem_to_u32(smem);
    int tid = threadIdx.x, mt = blockIdx.x;
    int warp = tid >> 5, lane = tid & 31;
    int mslice = warp >> 1, nslice = warp & 1;

    stage_async(g_wqh, g_wql, sb + OFF_B0, 25600, 64, tid);
    CP_COMMIT();
    stage_rows_f32(x + (size_t)mt * 128 * CDIM, 128, smem + OFF_AH, smem + OFF_AL, tid);
    CP_WAIT0();
    __syncthreads();

    for (int nt = 0; nt < 9; ++nt) {
        uint32_t cur = (nt & 1) ? OFF_B1 : OFF_B0;
        if (nt + 1 < 9) {
            uint32_t nxt = (nt & 1) ? OFF_B0 : OFF_B1;
            stage_async(g_wqh + (size_t)(nt + 1) * 64 * CDIM,
                        g_wql + (size_t)(nt + 1) * 64 * CDIM, sb + nxt, 25600, 64, tid);
            CP_COMMIT();
        }

        float acc[4][4];
        mma_core(sb, cur, mslice, nslice, lane, acc);

        int which = nt / 3;
        int rem0 = (nt - which * 3) * 64 + nslice * 32;
        size_t plane = (size_t)which * NW * NHD * 2048;
#pragma unroll
        for (int half = 0; half < 2; ++half) {
            int p = mt * 128 + mslice * 16 + (lane >> 2) + half * 8;
            int b = p >> 16, y = (p >> 8) & 255, xc = p & 255;
            int w = (b << 10) | ((y >> 3) << 5) | (xc >> 3);
            int t = ((y & 7) << 3) | (xc & 7);
            size_t base = plane + ((size_t)w * NHD) * 2048 + t * 32;
#pragma unroll
            for (int nf = 0; nf < 4; ++nf) {
                int rem = rem0 + nf * 8 + (lane & 3) * 2;
                int h = rem >> 5, d = rem & 31;
                *(float2*)(g_qkv + base + (size_t)h * 2048 + d) =
                    make_float2(acc[nf][half * 2], acc[nf][half * 2 + 1]);
            }
        }
        if (nt + 1 < 9) CP_WAIT0();
        __syncthreads();
    }
}

// ================= K2: windowed attention (core verbatim; bf16 hi/lo output) =================
__global__ __launch_bounds__(32) void k_attn(const float* __restrict__ rpb) {
    __shared__ float ks[2048], vs[2048], bias_s[240];
    int h = blockIdx.x, w = blockIdx.y, lane = threadIdx.x;
    size_t base = ((size_t)(w * NHD + h)) << 11;
    const size_t plane = (size_t)NW * NHD * 2048;
    const float4* kp4 = (const float4*)(g_qkv + plane + base);
    const float4* vp4 = (const float4*)(g_qkv + 2 * plane + base);
#pragma unroll
    for (int u = 0; u < 16; ++u) {
        ((float4*)ks)[(u << 5) + lane] = kp4[(u << 5) + lane];
        ((float4*)vs)[(u << 5) + lane] = vp4[(u << 5) + lane];
    }
    for (int i = lane; i < 225; i += 32) bias_s[i] = rpb[i * NHD + h];
    __syncthreads();

    int q0 = lane << 1, q1 = q0 + 1;
    ull qr0[16], qr1[16];
    const ull* qp = (const ull*)(g_qkv + base + (size_t)q0 * HD);
#pragma unroll
    for (int i = 0; i < 16; ++i) { qr0[i] = qp[i]; qr1[i] = qp[16 + i]; }

    int q0i = q0 >> 3, q0j = q0 & 7;
    int q1i = q1 >> 3, q1j = q1 & 7;
    ull acc0[16], acc1[16];
#pragma unroll
    for (int i = 0; i < 16; ++i) { acc0[i] = 0ull; acc1[i] = 0ull; }
    float sum0 = 0.0f, sum1 = 0.0f;

#pragma unroll 4
    for (int kk = 0; kk < 64; ++kk) {
        const ull* kr = (const ull*)(ks + (kk << 5));
        ull e00 = 0ull, e01 = 0ull, e10 = 0ull, e11 = 0ull;
#pragma unroll
        for (int i = 0; i < 8; ++i) {
            ull k0 = kr[2 * i], k1 = kr[2 * i + 1];
            fma2(e00, qr0[2 * i], k0);
            fma2(e01, qr0[2 * i + 1], k1);
            fma2(e10, qr1[2 * i], k0);
            fma2(e11, qr1[2 * i + 1], k1);
        }
        int ki = kk >> 3, kj = kk & 7;
        int bidx = (7 - ki) * 15 + (7 - kj);
        float2 f0 = unpk(add2(e00, e01));
        float2 f1 = unpk(add2(e10, e11));
        float p0 = __expf(f0.x + f0.y + bias_s[bidx + q0i * 15 + q0j]);
        float p1 = __expf(f1.x + f1.y + bias_s[bidx + q1i * 15 + q1j]);
        sum0 += p0; sum1 += p1;
        ull pv0 = dup2(p0), pv1 = dup2(p1);
        const ull* vr = (const ull*)(vs + (kk << 5));
#pragma unroll
        for (int i = 0; i < 16; ++i) {
            ull vv = vr[i];
            fma2(acc0[i], pv0, vv);
            fma2(acc1[i], pv1, vv);
        }
    }

    ull inv0 = dup2(1.0f / sum0), inv1 = dup2(1.0f / sum1);
    uint32_t hw0[16], lw0[16], hw1[16], lw1[16];
#pragma unroll
    for (int i = 0; i < 16; ++i) {
        float2 f = unpk(mul2(acc0[i], inv0));
        __nv_bfloat162 hh = __floats2bfloat162_rn(f.x, f.y);
        float2 hf = __bfloat1622float2(hh);
        __nv_bfloat162 ll = __floats2bfloat162_rn(f.x - hf.x, f.y - hf.y);
        hw0[i] = *(uint32_t*)&hh; lw0[i] = *(uint32_t*)&ll;
        f = unpk(mul2(acc1[i], inv1));
        hh = __floats2bfloat162_rn(f.x, f.y);
        hf = __bfloat1622float2(hh);
        ll = __floats2bfloat162_rn(f.x - hf.x, f.y - hf.y);
        hw1[i] = *(uint32_t*)&hh; lw1[i] = *(uint32_t*)&ll;
    }
    size_t r0 = ((size_t)w * WS2 + q0) * CDIM + h * HD;
    size_t r1 = ((size_t)w * WS2 + q1) * CDIM + h * HD;
#pragma unroll
    for (int i = 0; i < 4; ++i) {
        *(uint4*)(g_ath + r0 + i * 8) = ((uint4*)hw0)[i];
        *(uint4*)(g_atl + r0 + i * 8) = ((uint4*)lw0)[i];
        *(uint4*)(g_ath + r1 + i * 8) = ((uint4*)hw1)[i];
        *(uint4*)(g_atl + r1 + i * 8) = ((uint4*)lw1)[i];
    }
}

// ================= K3: proj GEMM + bias + pixel scatter =================
// grid(2048): 128 att rows per CTA; 512 thr; A and B both via cp.async.
__global__ __launch_bounds__(NTHR) void k_proj(const float* __restrict__ pb,
                                               float* __restrict__ out) {
    extern __shared__ char smem[];
    uint32_t sb = smem_to_u32(smem);
    int tid = threadIdx.x, mt = blockIdx.x;
    int warp = tid >> 5, lane = tid & 31;
    int mslice = warp >> 1, nslice = warp & 1;

    stage_async(g_wph, g_wpl, sb + OFF_B0, 25600, 64, tid);
    stage_async(g_ath + (size_t)mt * 128 * CDIM, g_atl + (size_t)mt * 128 * CDIM,
                sb + OFF_AH, OFF_AL - OFF_AH, 128, tid);
    CP_COMMIT();
    CP_WAIT0();
    __syncthreads();

    for (int nt = 0; nt < 3; ++nt) {
        uint32_t cur = (nt & 1) ? OFF_B1 : OFF_B0;
        if (nt + 1 < 3) {
            uint32_t nxt = (nt & 1) ? OFF_B0 : OFF_B1;
            stage_async(g_wph + (size_t)(nt + 1) * 64 * CDIM,
                        g_wpl + (size_t)(nt + 1) * 64 * CDIM, sb + nxt, 25600, 64, tid);
            CP_COMMIT();
        }

        float acc[4][4];
        mma_core(sb, cur, mslice, nslice, lane, acc);

#pragma unroll
        for (int half = 0; half < 2; ++half) {
            int p = mt * 128 + mslice * 16 + (lane >> 2) + half * 8;
            int w = p >> 6, t = p & 63;
            int b = w >> 10, wh = (w >> 5) & 31, ww = w & 31;
            int ri = t >> 3, ci = t & 7;
            size_t pix = (size_t)((b << 8) + (wh << 3) + ri) * 256 + (ww << 3) + ci;
            float* o = out + pix * CDIM;
#pragma unroll
            for (int nf = 0; nf < 4; ++nf) {
                int oc = nt * 64 + nslice * 32 + nf * 8 + (lane & 3) * 2;
                float2 bias = *(const float2*)(pb + oc);
                *(float2*)(o + oc) = make_float2(acc[nf][half * 2] + bias.x,
                                                 acc[nf][half * 2 + 1] + bias.y);
            }
        }
        if (nt + 1 < 3) CP_WAIT0();
        __syncthreads();
    }
}

// ================= launch =================
extern "C" void kernel_launch(void* const* d_in, const int* in_sizes, int n_in,
                              void* d_out, int out_size) {
    const float* x     = (const float*)d_in[0];
    const float* qkvw  = (const float*)d_in[1];
    const float* projw = (const float*)d_in[2];
    const float* pb    = (const float*)d_in[3];
    const float* rpb   = (const float*)d_in[4];
    (void)in_sizes; (void)n_in; (void)out_size;

    cudaFuncSetAttribute(k_qkv,  cudaFuncAttributeMaxDynamicSharedMemorySize, GEMM_SMEM);
    cudaFuncSetAttribute(k_proj, cudaFuncAttributeMaxDynamicSharedMemorySize, GEMM_SMEM);

    k_prep<<<768, 192>>>(qkvw, projw);
    k_qkv <<<2048, NTHR, GEMM_SMEM>>>(x);
    k_attn<<<dim3(NHD, NW), 32>>>(rpb);
    k_proj<<<2048, NTHR, GEMM_SMEM>>>(pb, (float*)d_out);
}

// round 15
// speedup vs baseline: 1.5340x; 1.2349x over previous
#include <cuda_runtime.h>
#include <cuda_bf16.h>
#include <cstdint>

#define NW   4096
#define NHD  6
#define HD   32
#define CDIM 192
#define WS2  64

// GEMM smem layout (bf16, row pitch 200 elems, ldmatrix conflict-free)
#define PITCH  200
#define OFF_AH 0
#define OFF_AL 51200
#define OFF_B0 102400            // buf: hi @ +0, lo @ +25600
#define OFF_B1 153600
#define GEMM_SMEM 204800
#define NTHR 512

// ---- scratch ----
__device__ __nv_bfloat16 g_qh[(size_t)NW * NHD * WS2 * HD], g_ql[(size_t)NW * NHD * WS2 * HD];
__device__ __nv_bfloat16 g_kh[(size_t)NW * NHD * WS2 * HD], g_kl[(size_t)NW * NHD * WS2 * HD];
__device__ __nv_bfloat16 g_vh[(size_t)NW * NHD * WS2 * HD], g_vl[(size_t)NW * NHD * WS2 * HD];
__device__ __nv_bfloat16 g_ath[(size_t)NW * WS2 * CDIM], g_atl[(size_t)NW * WS2 * CDIM];
__device__ __nv_bfloat16 g_wqh[576 * 192], g_wql[576 * 192];
__device__ __nv_bfloat16 g_wph[192 * 192], g_wpl[192 * 192];

// ================= helpers =================
__device__ __forceinline__ uint32_t smem_to_u32(const void* p) {
    uint32_t a;
    asm("{ .reg .u64 t; cvta.to.shared.u64 t, %1; cvt.u32.u64 %0, t; }" : "=r"(a) : "l"(p));
    return a;
}
__device__ __forceinline__ void ldsm4(uint32_t& r0, uint32_t& r1, uint32_t& r2, uint32_t& r3,
                                      uint32_t addr) {
    asm volatile("ldmatrix.sync.aligned.m8n8.x4.shared.b16 {%0,%1,%2,%3}, [%4];"
                 : "=r"(r0), "=r"(r1), "=r"(r2), "=r"(r3) : "r"(addr));
}
__device__ __forceinline__ void ldsm4t(uint32_t& r0, uint32_t& r1, uint32_t& r2, uint32_t& r3,
                                       uint32_t addr) {
    asm volatile("ldmatrix.sync.aligned.m8n8.x4.trans.shared.b16 {%0,%1,%2,%3}, [%4];"
                 : "=r"(r0), "=r"(r1), "=r"(r2), "=r"(r3) : "r"(addr));
}
__device__ __forceinline__ void mma16816(float* c, uint32_t a0, uint32_t a1, uint32_t a2,
                                         uint32_t a3, uint32_t b0, uint32_t b1) {
    asm volatile("mma.sync.aligned.m16n8k16.row.col.f32.bf16.bf16.f32 "
                 "{%0,%1,%2,%3}, {%4,%5,%6,%7}, {%8,%9}, {%0,%1,%2,%3};"
                 : "+f"(c[0]), "+f"(c[1]), "+f"(c[2]), "+f"(c[3])
                 : "r"(a0), "r"(a1), "r"(a2), "r"(a3), "r"(b0), "r"(b1));
}
#define CP_ASYNC16(dst, src) \
    asm volatile("cp.async.cg.shared.global [%0], [%1], 16;" :: "r"(dst), "l"(src) : "memory")
#define CP_COMMIT() asm volatile("cp.async.commit_group;" ::: "memory")
#define CP_WAIT0()  asm volatile("cp.async.wait_group 0;" ::: "memory")

// split two fp32 -> bf16x2 hi + bf16x2 lo
__device__ __forceinline__ void split2(float a, float b, uint32_t& hi, uint32_t& lo) {
    __nv_bfloat162 h = __floats2bfloat162_rn(a, b);
    float2 f = __bfloat1622float2(h);
    __nv_bfloat162 l = __floats2bfloat162_rn(a - f.x, b - f.y);
    hi = *(uint32_t*)&h;
    lo = *(uint32_t*)&l;
}

// ================= prep: weights fp32 -> bf16 hi/lo (q rows pre-scaled) =================
__global__ void k_prep(const float* __restrict__ qkvw, const float* __restrict__ projw) {
    int o = blockIdx.x, c = threadIdx.x;
    if (o < 576) {
        float v = qkvw[o * 192 + c];
        if (o < 192) v *= 0.17677669529663687f;
        __nv_bfloat16 h = __float2bfloat16(v);
        g_wqh[o * 192 + c] = h;
        g_wql[o * 192 + c] = __float2bfloat16(v - __bfloat162float(h));
    } else {
        int oo = o - 576;
        float v = projw[oo * 192 + c];
        __nv_bfloat16 h = __float2bfloat16(v);
        g_wph[oo * 192 + c] = h;
        g_wpl[oo * 192 + c] = __float2bfloat16(v - __bfloat162float(h));
    }
}

// ================= GEMM staging =================
__device__ __forceinline__ void cvt8(float4 v0, float4 v1, uint4& hi, uint4& lo) {
    __nv_bfloat162 h0 = __floats2bfloat162_rn(v0.x, v0.y);
    __nv_bfloat162 h1 = __floats2bfloat162_rn(v0.z, v0.w);
    __nv_bfloat162 h2 = __floats2bfloat162_rn(v1.x, v1.y);
    __nv_bfloat162 h3 = __floats2bfloat162_rn(v1.z, v1.w);
    float2 f0 = __bfloat1622float2(h0), f1 = __bfloat1622float2(h1);
    float2 f2 = __bfloat1622float2(h2), f3 = __bfloat1622float2(h3);
    __nv_bfloat162 l0 = __floats2bfloat162_rn(v0.x - f0.x, v0.y - f0.y);
    __nv_bfloat162 l1 = __floats2bfloat162_rn(v0.z - f1.x, v0.w - f1.y);
    __nv_bfloat162 l2 = __floats2bfloat162_rn(v1.x - f2.x, v1.y - f2.y);
    __nv_bfloat162 l3 = __floats2bfloat162_rn(v1.z - f3.x, v1.w - f3.y);
    hi = make_uint4(*(uint32_t*)&h0, *(uint32_t*)&h1, *(uint32_t*)&h2, *(uint32_t*)&h3);
    lo = make_uint4(*(uint32_t*)&l0, *(uint32_t*)&l1, *(uint32_t*)&l2, *(uint32_t*)&l3);
}

__device__ __forceinline__ void stage_rows_f32(const float* __restrict__ src, int nrows,
                                               char* dh, char* dl, int tid) {
    int groups = nrows * 24;
    for (int idx = tid; idx < groups; idx += NTHR) {
        int r = idx / 24, g = idx - r * 24;
        const float4* p = (const float4*)(src + (size_t)r * CDIM + g * 8);
        uint4 hi, lo;
        cvt8(p[0], p[1], hi, lo);
        uint32_t o = (uint32_t)(r * PITCH + g * 8) * 2;
        *(uint4*)(dh + o) = hi;
        *(uint4*)(dl + o) = lo;
    }
}

__device__ __forceinline__ void stage_async(const __nv_bfloat16* __restrict__ sh,
                                            const __nv_bfloat16* __restrict__ sl,
                                            uint32_t dbuf, uint32_t lo_delta,
                                            int nrows, int tid) {
    int groups = nrows * 24;
    for (int idx = tid; idx < groups; idx += NTHR) {
        int r = idx / 24, g = idx - r * 24;
        uint32_t o = (uint32_t)(r * PITCH + g * 8) * 2;
        CP_ASYNC16(dbuf + o, sh + (size_t)r * CDIM + g * 8);
        CP_ASYNC16(dbuf + lo_delta + o, sl + (size_t)r * CDIM + g * 8);
    }
}

// ================= GEMM warp mma core: 16x32 per warp over K=192, split-bf16 =================
__device__ __forceinline__ void mma_core(uint32_t sb, uint32_t bbuf, int mslice, int nslice,
                                         int lane, float acc[4][4]) {
#pragma unroll
    for (int nf = 0; nf < 4; ++nf)
#pragma unroll
        for (int j = 0; j < 4; ++j) acc[nf][j] = 0.0f;

    const uint32_t aoff = (uint32_t)((mslice * 16 + (lane & 15)) * PITCH + (lane >> 4) * 8) * 2;
    const uint32_t boff = (uint32_t)((nslice * 32 + (lane & 7) + ((lane >> 4) << 3)) * PITCH
                                     + ((lane >> 3) & 1) * 8) * 2;
    const uint32_t aAh = sb + OFF_AH + aoff, aAl = sb + OFF_AL + aoff;
    const uint32_t aBh = sb + bbuf + boff,   aBl = sb + bbuf + 25600 + boff;

#pragma unroll 2
    for (int kc = 0; kc < 12; ++kc) {
        uint32_t ko = kc * 32;
        uint32_t ah[4], al[4], bh[4][2], bl[4][2];
        ldsm4(ah[0], ah[1], ah[2], ah[3], aAh + ko);
        ldsm4(al[0], al[1], al[2], al[3], aAl + ko);
#pragma unroll
        for (int np = 0; np < 2; ++np) {
            ldsm4(bh[2 * np][0], bh[2 * np][1], bh[2 * np + 1][0], bh[2 * np + 1][1],
                  aBh + np * (16 * PITCH * 2) + ko);
            ldsm4(bl[2 * np][0], bl[2 * np][1], bl[2 * np + 1][0], bl[2 * np + 1][1],
                  aBl + np * (16 * PITCH * 2) + ko);
        }
#pragma unroll
        for (int nf = 0; nf < 4; ++nf) {
            mma16816(acc[nf], ah[0], ah[1], ah[2], ah[3], bh[nf][0], bh[nf][1]);
            mma16816(acc[nf], ah[0], ah[1], ah[2], ah[3], bl[nf][0], bl[nf][1]);
            mma16816(acc[nf], al[0], al[1], al[2], al[3], bh[nf][0], bh[nf][1]);
        }
    }
}

// ================= K1: QKV GEMM -> bf16 hi/lo q/k/v planes =================
__global__ __launch_bounds__(NTHR) void k_qkv(const float* __restrict__ x) {
    extern __shared__ char smem[];
    uint32_t sb = smem_to_u32(smem);
    int tid = threadIdx.x, mt = blockIdx.x;
    int warp = tid >> 5, lane = tid & 31;
    int mslice = warp >> 1, nslice = warp & 1;

    stage_async(g_wqh, g_wql, sb + OFF_B0, 25600, 64, tid);
    CP_COMMIT();
    stage_rows_f32(x + (size_t)mt * 128 * CDIM, 128, smem + OFF_AH, smem + OFF_AL, tid);
    CP_WAIT0();
    __syncthreads();

    for (int nt = 0; nt < 9; ++nt) {
        uint32_t cur = (nt & 1) ? OFF_B1 : OFF_B0;
        if (nt + 1 < 9) {
            uint32_t nxt = (nt & 1) ? OFF_B0 : OFF_B1;
            stage_async(g_wqh + (size_t)(nt + 1) * 64 * CDIM,
                        g_wql + (size_t)(nt + 1) * 64 * CDIM, sb + nxt, 25600, 64, tid);
            CP_COMMIT();
        }

        float acc[4][4];
        mma_core(sb, cur, mslice, nslice, lane, acc);

        int which = nt / 3;
        int rem0 = (nt - which * 3) * 64 + nslice * 32;
        __nv_bfloat16* dh = (which == 0) ? g_qh : (which == 1) ? g_kh : g_vh;
        __nv_bfloat16* dl = (which == 0) ? g_ql : (which == 1) ? g_kl : g_vl;
#pragma unroll
        for (int half = 0; half < 2; ++half) {
            int p = mt * 128 + mslice * 16 + (lane >> 2) + half * 8;
            int b = p >> 16, y = (p >> 8) & 255, xc = p & 255;
            int w = (b << 10) | ((y >> 3) << 5) | (xc >> 3);
            int t = ((y & 7) << 3) | (xc & 7);
            size_t base = ((size_t)(w * NHD)) * 2048 + t * 32;
#pragma unroll
            for (int nf = 0; nf < 4; ++nf) {
                int rem = rem0 + nf * 8 + (lane & 3) * 2;
                int h = rem >> 5, d = rem & 31;
                uint32_t hi, lo;
                split2(acc[nf][half * 2], acc[nf][half * 2 + 1], hi, lo);
                size_t e = base + (size_t)h * 2048 + d;
                *(uint32_t*)(dh + e) = hi;
                *(uint32_t*)(dl + e) = lo;
            }
        }
        if (nt + 1 < 9) CP_WAIT0();
        __syncthreads();
    }
}

// ================= K2: tensorized windowed attention =================
// grid(6, 4096): x = head, y = window. 128 thr / 4 warps; warp = 16 query rows.
#define APITCH 40
__global__ __launch_bounds__(128) void k_attn(const float* __restrict__ rpb) {
    __shared__ __align__(16) __nv_bfloat16 smQ[2][64 * APITCH];
    __shared__ __align__(16) __nv_bfloat16 smK[2][64 * APITCH];
    __shared__ __align__(16) __nv_bfloat16 smV[2][64 * APITCH];
    __shared__ float bias_s[240];

    int h = blockIdx.x, w = blockIdx.y;
    int tid = threadIdx.x, warp = tid >> 5, lane = tid & 31;
    size_t base = ((size_t)(w * NHD + h)) * 2048;   // [w][h][64][32]

    // stage 6 tiles via cp.async: 64 rows x 32 bf16 -> pitch 40
    {
        const __nv_bfloat16* srcs[6] = {g_qh + base, g_ql + base, g_kh + base,
                                        g_kl + base, g_vh + base, g_vl + base};
        uint32_t dsts[6] = {smem_to_u32(smQ[0]), smem_to_u32(smQ[1]),
                            smem_to_u32(smK[0]), smem_to_u32(smK[1]),
                            smem_to_u32(smV[0]), smem_to_u32(smV[1])};
#pragma unroll
        for (int tl = 0; tl < 6; ++tl) {
#pragma unroll
            for (int i = 0; i < 2; ++i) {
                int idx = i * 128 + tid;          // 256 chunks of 16B
                int r = idx >> 2, seg = idx & 3;
                CP_ASYNC16(dsts[tl] + (uint32_t)(r * APITCH + seg * 8) * 2,
                           srcs[tl] + r * 32 + seg * 8);
            }
        }
        CP_COMMIT();
    }
    for (int i = tid; i < 225; i += 128) bias_s[i] = rpb[i * NHD + h];
    CP_WAIT0();
    __syncthreads();

    uint32_t sq0 = smem_to_u32(smQ[0]), sq1 = smem_to_u32(smQ[1]);
    uint32_t sk0 = smem_to_u32(smK[0]), sk1 = smem_to_u32(smK[1]);
    uint32_t sv0 = smem_to_u32(smV[0]), sv1 = smem_to_u32(smV[1]);

    // ---- S = Q @ K^T (split-bf16 3-term), M=64/warp16, N=64, K=32 ----
    uint32_t qh_[2][4], ql_[2][4];
    const uint32_t qoff = (uint32_t)((warp * 16 + (lane & 15)) * APITCH + (lane >> 4) * 8) * 2;
#pragma unroll
    for (int kc = 0; kc < 2; ++kc) {
        ldsm4(qh_[kc][0], qh_[kc][1], qh_[kc][2], qh_[kc][3], sq0 + qoff + kc * 32);
        ldsm4(ql_[kc][0], ql_[kc][1], ql_[kc][2], ql_[kc][3], sq1 + qoff + kc * 32);
    }

    float s[8][4];
#pragma unroll
    for (int nf = 0; nf < 8; ++nf)
#pragma unroll
        for (int j = 0; j < 4; ++j) s[nf][j] = 0.0f;

    const uint32_t koff = (uint32_t)(((lane & 7) + ((lane >> 4) << 3)) * APITCH
                                     + ((lane >> 3) & 1) * 8) * 2;
#pragma unroll
    for (int kc = 0; kc < 2; ++kc) {
        uint32_t bh[8][2], bl[8][2];
#pragma unroll
        for (int np = 0; np < 4; ++np) {
            uint32_t ao = koff + (uint32_t)(np * 16 * APITCH) * 2 + kc * 32;
            ldsm4(bh[2 * np][0], bh[2 * np][1], bh[2 * np + 1][0], bh[2 * np + 1][1], sk0 + ao);
            ldsm4(bl[2 * np][0], bl[2 * np][1], bl[2 * np + 1][0], bl[2 * np + 1][1], sk1 + ao);
        }
#pragma unroll
        for (int nf = 0; nf < 8; ++nf) {
            mma16816(s[nf], qh_[kc][0], qh_[kc][1], qh_[kc][2], qh_[kc][3], bh[nf][0], bh[nf][1]);
            mma16816(s[nf], qh_[kc][0], qh_[kc][1], qh_[kc][2], qh_[kc][3], bl[nf][0], bl[nf][1]);
            mma16816(s[nf], ql_[kc][0], ql_[kc][1], ql_[kc][2], ql_[kc][3], bh[nf][0], bh[nf][1]);
        }
    }

    // ---- bias + exp + row sums (no-max softmax, |s| small) ----
    int r0 = warp * 16 + (lane >> 2), r1 = r0 + 8;
    int c0base = (lane & 3) * 2;
    float sum0 = 0.0f, sum1 = 0.0f;
#pragma unroll
    for (int nf = 0; nf < 8; ++nf) {
        int c0 = nf * 8 + c0base, c1 = c0 + 1;
        float p00 = __expf(s[nf][0] + bias_s[((r0 >> 3) - (c0 >> 3) + 7) * 15 + (r0 & 7) - (c0 & 7) + 7]);
        float p01 = __expf(s[nf][1] + bias_s[((r0 >> 3) - (c1 >> 3) + 7) * 15 + (r0 & 7) - (c1 & 7) + 7]);
        float p10 = __expf(s[nf][2] + bias_s[((r1 >> 3) - (c0 >> 3) + 7) * 15 + (r1 & 7) - (c0 & 7) + 7]);
        float p11 = __expf(s[nf][3] + bias_s[((r1 >> 3) - (c1 >> 3) + 7) * 15 + (r1 & 7) - (c1 & 7) + 7]);
        s[nf][0] = p00; s[nf][1] = p01; s[nf][2] = p10; s[nf][3] = p11;
        sum0 += p00 + p01;
        sum1 += p10 + p11;
    }
    sum0 += __shfl_xor_sync(0xffffffffu, sum0, 1);
    sum0 += __shfl_xor_sync(0xffffffffu, sum0, 2);
    sum1 += __shfl_xor_sync(0xffffffffu, sum1, 1);
    sum1 += __shfl_xor_sync(0xffffffffu, sum1, 2);

    // ---- P fragments (A-layout), split hi/lo ----
    uint32_t ph[4][4], pl[4][4];
#pragma unroll
    for (int k2 = 0; k2 < 4; ++k2) {
        split2(s[2 * k2][0],     s[2 * k2][1],     ph[k2][0], pl[k2][0]);
        split2(s[2 * k2][2],     s[2 * k2][3],     ph[k2][1], pl[k2][1]);
        split2(s[2 * k2 + 1][0], s[2 * k2 + 1][1], ph[k2][2], pl[k2][2]);
        split2(s[2 * k2 + 1][2], s[2 * k2 + 1][3], ph[k2][3], pl[k2][3]);
    }

    // ---- O = P @ V (V via ldmatrix.trans), N=32 ----
    float o[4][4];
#pragma unroll
    for (int nf = 0; nf < 4; ++nf)
#pragma unroll
        for (int j = 0; j < 4; ++j) o[nf][j] = 0.0f;

#pragma unroll
    for (int k2 = 0; k2 < 4; ++k2) {
        int key = k2 * 16 + ((lane >> 3) & 1) * 8 + (lane & 7);
#pragma unroll
        for (int dp = 0; dp < 2; ++dp) {
            uint32_t ao = (uint32_t)(key * APITCH + dp * 16 + (lane >> 4) * 8) * 2;
            uint32_t vh0, vh1, vh2, vh3, vl0, vl1, vl2, vl3;
            ldsm4t(vh0, vh1, vh2, vh3, sv0 + ao);
            ldsm4t(vl0, vl1, vl2, vl3, sv1 + ao);
            mma16816(o[2 * dp],     ph[k2][0], ph[k2][1], ph[k2][2], ph[k2][3], vh0, vh1);
            mma16816(o[2 * dp],     ph[k2][0], ph[k2][1], ph[k2][2], ph[k2][3], vl0, vl1);
            mma16816(o[2 * dp],     pl[k2][0], pl[k2][1], pl[k2][2], pl[k2][3], vh0, vh1);
            mma16816(o[2 * dp + 1], ph[k2][0], ph[k2][1], ph[k2][2], ph[k2][3], vh2, vh3);
            mma16816(o[2 * dp + 1], ph[k2][0], ph[k2][1], ph[k2][2], ph[k2][3], vl2, vl3);
            mma16816(o[2 * dp + 1], pl[k2][0], pl[k2][1], pl[k2][2], pl[k2][3], vh2, vh3);
        }
    }

    // ---- normalize + emit bf16 hi/lo to g_ath/g_atl ----
    float inv0 = 1.0f / sum0, inv1 = 1.0f / sum1;
    size_t row0 = ((size_t)w * WS2 + r0) * CDIM + h * HD;
    size_t row1 = ((size_t)w * WS2 + r1) * CDIM + h * HD;
#pragma unroll
    for (int nf = 0; nf < 4; ++nf) {
        int d = nf * 8 + c0base;
        uint32_t hi, lo;
        split2(o[nf][0] * inv0, o[nf][1] * inv0, hi, lo);
        *(uint32_t*)(g_ath + row0 + d) = hi;
        *(uint32_t*)(g_atl + row0 + d) = lo;
        split2(o[nf][2] * inv1, o[nf][3] * inv1, hi, lo);
        *(uint32_t*)(g_ath + row1 + d) = hi;
        *(uint32_t*)(g_atl + row1 + d) = lo;
    }
}

// ================= K3: proj GEMM + bias + pixel scatter (R14 verbatim) =================
__global__ __launch_bounds__(NTHR) void k_proj(const float* __restrict__ pb,
                                               float* __restrict__ out) {
    extern __shared__ char smem[];
    uint32_t sb = smem_to_u32(smem);
    int tid = threadIdx.x, mt = blockIdx.x;
    int warp = tid >> 5, lane = tid & 31;
    int mslice = warp >> 1, nslice = warp & 1;

    stage_async(g_wph, g_wpl, sb + OFF_B0, 25600, 64, tid);
    stage_async(g_ath + (size_t)mt * 128 * CDIM, g_atl + (size_t)mt * 128 * CDIM,
                sb + OFF_AH, OFF_AL - OFF_AH, 128, tid);
    CP_COMMIT();
    CP_WAIT0();
    __syncthreads();

    for (int nt = 0; nt < 3; ++nt) {
        uint32_t cur = (nt & 1) ? OFF_B1 : OFF_B0;
        if (nt + 1 < 3) {
            uint32_t nxt = (nt & 1) ? OFF_B0 : OFF_B1;
            stage_async(g_wph + (size_t)(nt + 1) * 64 * CDIM,
                        g_wpl + (size_t)(nt + 1) * 64 * CDIM, sb + nxt, 25600, 64, tid);
            CP_COMMIT();
        }

        float acc[4][4];
        mma_core(sb, cur, mslice, nslice, lane, acc);

#pragma unroll
        for (int half = 0; half < 2; ++half) {
            int p = mt * 128 + mslice * 16 + (lane >> 2) + half * 8;
            int w = p >> 6, t = p & 63;
            int b = w >> 10, wh = (w >> 5) & 31, ww = w & 31;
            int ri = t >> 3, ci = t & 7;
            size_t pix = (size_t)((b << 8) + (wh << 3) + ri) * 256 + (ww << 3) + ci;
            float* o = out + pix * CDIM;
#pragma unroll
            for (int nf = 0; nf < 4; ++nf) {
                int oc = nt * 64 + nslice * 32 + nf * 8 + (lane & 3) * 2;
                float2 bias = *(const float2*)(pb + oc);
                *(float2*)(o + oc) = make_float2(acc[nf][half * 2] + bias.x,
                                                 acc[nf][half * 2 + 1] + bias.y);
            }
        }
        if (nt + 1 < 3) CP_WAIT0();
        __syncthreads();
    }
}

// ================= launch =================
extern "C" void kernel_launch(void* const* d_in, const int* in_sizes, int n_in,
                              void* d_out, int out_size) {
    const float* x     = (const float*)d_in[0];
    const float* qkvw  = (const float*)d_in[1];
    const float* projw = (const float*)d_in[2];
    const float* pb    = (const float*)d_in[3];
    const float* rpb   = (const float*)d_in[4];
    (void)in_sizes; (void)n_in; (void)out_size;

    cudaFuncSetAttribute(k_qkv,  cudaFuncAttributeMaxDynamicSharedMemorySize, GEMM_SMEM);
    cudaFuncSetAttribute(k_proj, cudaFuncAttributeMaxDynamicSharedMemorySize, GEMM_SMEM);

    k_prep<<<768, 192>>>(qkvw, projw);
    k_qkv <<<2048, NTHR, GEMM_SMEM>>>(x);
    k_attn<<<dim3(NHD, NW), 128>>>(rpb);
    k_proj<<<2048, NTHR, GEMM_SMEM>>>(pb, (float*)d_out);
}

// round 16
// speedup vs baseline: 1.5776x; 1.0284x over previous
#include <cuda_runtime.h>
#include <cuda_bf16.h>
#include <cstdint>

#define NW   4096
#define NHD  6
#define HD   32
#define CDIM 192
#define WS2  64

// GEMM smem layout (bf16, row pitch 200 elems, ldmatrix conflict-free)
#define PITCH  200
#define OFF_AH 0
#define OFF_AL 51200
#define OFF_B0 102400            // buf: hi @ +0, lo @ +25600
#define OFF_B1 153600
#define GEMM_SMEM 204800
#define NTHR 512

// ---- scratch ----
__device__ __nv_bfloat16 g_qh[(size_t)NW * NHD * WS2 * HD], g_ql[(size_t)NW * NHD * WS2 * HD];
__device__ __nv_bfloat16 g_kh[(size_t)NW * NHD * WS2 * HD], g_kl[(size_t)NW * NHD * WS2 * HD];
__device__ __nv_bfloat16 g_vh[(size_t)NW * NHD * WS2 * HD], g_vl[(size_t)NW * NHD * WS2 * HD];
__device__ __nv_bfloat16 g_ath[(size_t)NW * WS2 * CDIM], g_atl[(size_t)NW * WS2 * CDIM];
__device__ __nv_bfloat16 g_wqh[576 * 192], g_wql[576 * 192];
__device__ __nv_bfloat16 g_wph[192 * 192], g_wpl[192 * 192];

// ================= helpers =================
__device__ __forceinline__ uint32_t smem_to_u32(const void* p) {
    uint32_t a;
    asm("{ .reg .u64 t; cvta.to.shared.u64 t, %1; cvt.u32.u64 %0, t; }" : "=r"(a) : "l"(p));
    return a;
}
__device__ __forceinline__ void ldsm4(uint32_t& r0, uint32_t& r1, uint32_t& r2, uint32_t& r3,
                                      uint32_t addr) {
    asm volatile("ldmatrix.sync.aligned.m8n8.x4.shared.b16 {%0,%1,%2,%3}, [%4];"
                 : "=r"(r0), "=r"(r1), "=r"(r2), "=r"(r3) : "r"(addr));
}
__device__ __forceinline__ void ldsm4t(uint32_t& r0, uint32_t& r1, uint32_t& r2, uint32_t& r3,
                                       uint32_t addr) {
    asm volatile("ldmatrix.sync.aligned.m8n8.x4.trans.shared.b16 {%0,%1,%2,%3}, [%4];"
                 : "=r"(r0), "=r"(r1), "=r"(r2), "=r"(r3) : "r"(addr));
}
__device__ __forceinline__ void mma16816(float* c, uint32_t a0, uint32_t a1, uint32_t a2,
                                         uint32_t a3, uint32_t b0, uint32_t b1) {
    asm volatile("mma.sync.aligned.m16n8k16.row.col.f32.bf16.bf16.f32 "
                 "{%0,%1,%2,%3}, {%4,%5,%6,%7}, {%8,%9}, {%0,%1,%2,%3};"
                 : "+f"(c[0]), "+f"(c[1]), "+f"(c[2]), "+f"(c[3])
                 : "r"(a0), "r"(a1), "r"(a2), "r"(a3), "r"(b0), "r"(b1));
}
#define CP_ASYNC16(dst, src) \
    asm volatile("cp.async.cg.shared.global [%0], [%1], 16;" :: "r"(dst), "l"(src) : "memory")
#define CP_COMMIT() asm volatile("cp.async.commit_group;" ::: "memory")
#define CP_WAIT0()  asm volatile("cp.async.wait_group 0;" ::: "memory")

__device__ __forceinline__ void split2(float a, float b, uint32_t& hi, uint32_t& lo) {
    __nv_bfloat162 h = __floats2bfloat162_rn(a, b);
    float2 f = __bfloat1622float2(h);
    __nv_bfloat162 l = __floats2bfloat162_rn(a - f.x, b - f.y);
    hi = *(uint32_t*)&h;
    lo = *(uint32_t*)&l;
}

// ================= prep: weights fp32 -> bf16 hi/lo (q rows pre-scaled) =================
__global__ void k_prep(const float* __restrict__ qkvw, const float* __restrict__ projw) {
    int o = blockIdx.x, c = threadIdx.x;
    if (o < 576) {
        float v = qkvw[o * 192 + c];
        if (o < 192) v *= 0.17677669529663687f;
        __nv_bfloat16 h = __float2bfloat16(v);
        g_wqh[o * 192 + c] = h;
        g_wql[o * 192 + c] = __float2bfloat16(v - __bfloat162float(h));
    } else {
        int oo = o - 576;
        float v = projw[oo * 192 + c];
        __nv_bfloat16 h = __float2bfloat16(v);
        g_wph[oo * 192 + c] = h;
        g_wpl[oo * 192 + c] = __float2bfloat16(v - __bfloat162float(h));
    }
}

// ================= GEMM staging =================
__device__ __forceinline__ void cvt8(float4 v0, float4 v1, uint4& hi, uint4& lo) {
    __nv_bfloat162 h0 = __floats2bfloat162_rn(v0.x, v0.y);
    __nv_bfloat162 h1 = __floats2bfloat162_rn(v0.z, v0.w);
    __nv_bfloat162 h2 = __floats2bfloat162_rn(v1.x, v1.y);
    __nv_bfloat162 h3 = __floats2bfloat162_rn(v1.z, v1.w);
    float2 f0 = __bfloat1622float2(h0), f1 = __bfloat1622float2(h1);
    float2 f2 = __bfloat1622float2(h2), f3 = __bfloat1622float2(h3);
    __nv_bfloat162 l0 = __floats2bfloat162_rn(v0.x - f0.x, v0.y - f0.y);
    __nv_bfloat162 l1 = __floats2bfloat162_rn(v0.z - f1.x, v0.w - f1.y);
    __nv_bfloat162 l2 = __floats2bfloat162_rn(v1.x - f2.x, v1.y - f2.y);
    __nv_bfloat162 l3 = __floats2bfloat162_rn(v1.z - f3.x, v1.w - f3.y);
    hi = make_uint4(*(uint32_t*)&h0, *(uint32_t*)&h1, *(uint32_t*)&h2, *(uint32_t*)&h3);
    lo = make_uint4(*(uint32_t*)&l0, *(uint32_t*)&l1, *(uint32_t*)&l2, *(uint32_t*)&l3);
}

__device__ __forceinline__ void stage_rows_f32(const float* __restrict__ src, int nrows,
                                               char* dh, char* dl, int tid) {
    int groups = nrows * 24;
    for (int idx = tid; idx < groups; idx += NTHR) {
        int r = idx / 24, g = idx - r * 24;
        const float4* p = (const float4*)(src + (size_t)r * CDIM + g * 8);
        uint4 hi, lo;
        cvt8(p[0], p[1], hi, lo);
        uint32_t o = (uint32_t)(r * PITCH + g * 8) * 2;
        *(uint4*)(dh + o) = hi;
        *(uint4*)(dl + o) = lo;
    }
}

__device__ __forceinline__ void stage_async(const __nv_bfloat16* __restrict__ sh,
                                            const __nv_bfloat16* __restrict__ sl,
                                            uint32_t dbuf, uint32_t lo_delta,
                                            int nrows, int tid) {
    int groups = nrows * 24;
    for (int idx = tid; idx < groups; idx += NTHR) {
        int r = idx / 24, g = idx - r * 24;
        uint32_t o = (uint32_t)(r * PITCH + g * 8) * 2;
        CP_ASYNC16(dbuf + o, sh + (size_t)r * CDIM + g * 8);
        CP_ASYNC16(dbuf + lo_delta + o, sl + (size_t)r * CDIM + g * 8);
    }
}

// ================= GEMM warp mma core: 16x32/warp, K=192, split-bf16, SW-pipelined =================
__device__ __forceinline__ void ld_frags(uint32_t aAh, uint32_t aAl, uint32_t aBh, uint32_t aBl,
                                         uint32_t ko, uint32_t ah[4], uint32_t al[4],
                                         uint32_t bh[4][2], uint32_t bl[4][2]) {
    ldsm4(ah[0], ah[1], ah[2], ah[3], aAh + ko);
    ldsm4(al[0], al[1], al[2], al[3], aAl + ko);
#pragma unroll
    for (int np = 0; np < 2; ++np) {
        ldsm4(bh[2 * np][0], bh[2 * np][1], bh[2 * np + 1][0], bh[2 * np + 1][1],
              aBh + np * (16 * PITCH * 2) + ko);
        ldsm4(bl[2 * np][0], bl[2 * np][1], bl[2 * np + 1][0], bl[2 * np + 1][1],
              aBl + np * (16 * PITCH * 2) + ko);
    }
}

__device__ __forceinline__ void mma_core(uint32_t sb, uint32_t bbuf, int mslice, int nslice,
                                         int lane, float acc[4][4]) {
#pragma unroll
    for (int nf = 0; nf < 4; ++nf)
#pragma unroll
        for (int j = 0; j < 4; ++j) acc[nf][j] = 0.0f;

    const uint32_t aoff = (uint32_t)((mslice * 16 + (lane & 15)) * PITCH + (lane >> 4) * 8) * 2;
    const uint32_t boff = (uint32_t)((nslice * 32 + (lane & 7) + ((lane >> 4) << 3)) * PITCH
                                     + ((lane >> 3) & 1) * 8) * 2;
    const uint32_t aAh = sb + OFF_AH + aoff, aAl = sb + OFF_AL + aoff;
    const uint32_t aBh = sb + bbuf + boff,   aBl = sb + bbuf + 25600 + boff;

    uint32_t ah[2][4], al[2][4], bh[2][4][2], bl[2][4][2];
    ld_frags(aAh, aAl, aBh, aBl, 0, ah[0], al[0], bh[0], bl[0]);
#pragma unroll
    for (int kc = 0; kc < 12; ++kc) {
        int cur = kc & 1;
        if (kc < 11)
            ld_frags(aAh, aAl, aBh, aBl, (kc + 1) * 32,
                     ah[cur ^ 1], al[cur ^ 1], bh[cur ^ 1], bl[cur ^ 1]);
#pragma unroll
        for (int nf = 0; nf < 4; ++nf) {
            mma16816(acc[nf], ah[cur][0], ah[cur][1], ah[cur][2], ah[cur][3],
                     bh[cur][nf][0], bh[cur][nf][1]);
            mma16816(acc[nf], ah[cur][0], ah[cur][1], ah[cur][2], ah[cur][3],
                     bl[cur][nf][0], bl[cur][nf][1]);
            mma16816(acc[nf], al[cur][0], al[cur][1], al[cur][2], al[cur][3],
                     bh[cur][nf][0], bh[cur][nf][1]);
        }
    }
}

// ================= K1: QKV GEMM -> bf16 hi/lo q/k/v planes =================
__global__ __launch_bounds__(NTHR) void k_qkv(const float* __restrict__ x) {
    extern __shared__ char smem[];
    uint32_t sb = smem_to_u32(smem);
    int tid = threadIdx.x, mt = blockIdx.x;
    int warp = tid >> 5, lane = tid & 31;
    int mslice = warp >> 1, nslice = warp & 1;

    stage_async(g_wqh, g_wql, sb + OFF_B0, 25600, 64, tid);
    CP_COMMIT();
    stage_rows_f32(x + (size_t)mt * 128 * CDIM, 128, smem + OFF_AH, smem + OFF_AL, tid);
    CP_WAIT0();
    __syncthreads();

    for (int nt = 0; nt < 9; ++nt) {
        uint32_t cur = (nt & 1) ? OFF_B1 : OFF_B0;
        if (nt + 1 < 9) {
            uint32_t nxt = (nt & 1) ? OFF_B0 : OFF_B1;
            stage_async(g_wqh + (size_t)(nt + 1) * 64 * CDIM,
                        g_wql + (size_t)(nt + 1) * 64 * CDIM, sb + nxt, 25600, 64, tid);
            CP_COMMIT();
        }

        float acc[4][4];
        mma_core(sb, cur, mslice, nslice, lane, acc);

        int which = nt / 3;
        int rem0 = (nt - which * 3) * 64 + nslice * 32;
        __nv_bfloat16* dh = (which == 0) ? g_qh : (which == 1) ? g_kh : g_vh;
        __nv_bfloat16* dl = (which == 0) ? g_ql : (which == 1) ? g_kl : g_vl;
#pragma unroll
        for (int half = 0; half < 2; ++half) {
            int p = mt * 128 + mslice * 16 + (lane >> 2) + half * 8;
            int b = p >> 16, y = (p >> 8) & 255, xc = p & 255;
            int w = (b << 10) | ((y >> 3) << 5) | (xc >> 3);
            int t = ((y & 7) << 3) | (xc & 7);
            size_t base = ((size_t)(w * NHD)) * 2048 + t * 32;
#pragma unroll
            for (int nf = 0; nf < 4; ++nf) {
                int rem = rem0 + nf * 8 + (lane & 3) * 2;
                int h = rem >> 5, d = rem & 31;
                uint32_t hi, lo;
                split2(acc[nf][half * 2], acc[nf][half * 2 + 1], hi, lo);
                size_t e = base + (size_t)h * 2048 + d;
                *(uint32_t*)(dh + e) = hi;
                *(uint32_t*)(dl + e) = lo;
            }
        }
        if (nt + 1 < 9) CP_WAIT0();
        __syncthreads();
    }
}

// ================= K2: tensorized windowed attention (R15 verbatim) =================
#define APITCH 40
__global__ __launch_bounds__(128) void k_attn(const float* __restrict__ rpb) {
    __shared__ __align__(16) __nv_bfloat16 smQ[2][64 * APITCH];
    __shared__ __align__(16) __nv_bfloat16 smK[2][64 * APITCH];
    __shared__ __align__(16) __nv_bfloat16 smV[2][64 * APITCH];
    __shared__ float bias_s[240];

    int h = blockIdx.x, w = blockIdx.y;
    int tid = threadIdx.x, warp = tid >> 5, lane = tid & 31;
    size_t base = ((size_t)(w * NHD + h)) * 2048;

    {
        const __nv_bfloat16* srcs[6] = {g_qh + base, g_ql + base, g_kh + base,
                                        g_kl + base, g_vh + base, g_vl + base};
        uint32_t dsts[6] = {smem_to_u32(smQ[0]), smem_to_u32(smQ[1]),
                            smem_to_u32(smK[0]), smem_to_u32(smK[1]),
                            smem_to_u32(smV[0]), smem_to_u32(smV[1])};
#pragma unroll
        for (int tl = 0; tl < 6; ++tl) {
#pragma unroll
            for (int i = 0; i < 2; ++i) {
                int idx = i * 128 + tid;
                int r = idx >> 2, seg = idx & 3;
                CP_ASYNC16(dsts[tl] + (uint32_t)(r * APITCH + seg * 8) * 2,
                           srcs[tl] + r * 32 + seg * 8);
            }
        }
        CP_COMMIT();
    }
    for (int i = tid; i < 225; i += 128) bias_s[i] = rpb[i * NHD + h];
    CP_WAIT0();
    __syncthreads();

    uint32_t sq0 = smem_to_u32(smQ[0]), sq1 = smem_to_u32(smQ[1]);
    uint32_t sk0 = smem_to_u32(smK[0]), sk1 = smem_to_u32(smK[1]);
    uint32_t sv0 = smem_to_u32(smV[0]), sv1 = smem_to_u32(smV[1]);

    uint32_t qh_[2][4], ql_[2][4];
    const uint32_t qoff = (uint32_t)((warp * 16 + (lane & 15)) * APITCH + (lane >> 4) * 8) * 2;
#pragma unroll
    for (int kc = 0; kc < 2; ++kc) {
        ldsm4(qh_[kc][0], qh_[kc][1], qh_[kc][2], qh_[kc][3], sq0 + qoff + kc * 32);
        ldsm4(ql_[kc][0], ql_[kc][1], ql_[kc][2], ql_[kc][3], sq1 + qoff + kc * 32);
    }

    float s[8][4];
#pragma unroll
    for (int nf = 0; nf < 8; ++nf)
#pragma unroll
        for (int j = 0; j < 4; ++j) s[nf][j] = 0.0f;

    const uint32_t koff = (uint32_t)(((lane & 7) + ((lane >> 4) << 3)) * APITCH
                                     + ((lane >> 3) & 1) * 8) * 2;
#pragma unroll
    for (int kc = 0; kc < 2; ++kc) {
        uint32_t bh[8][2], bl[8][2];
#pragma unroll
        for (int np = 0; np < 4; ++np) {
            uint32_t ao = koff + (uint32_t)(np * 16 * APITCH) * 2 + kc * 32;
            ldsm4(bh[2 * np][0], bh[2 * np][1], bh[2 * np + 1][0], bh[2 * np + 1][1], sk0 + ao);
            ldsm4(bl[2 * np][0], bl[2 * np][1], bl[2 * np + 1][0], bl[2 * np + 1][1], sk1 + ao);
        }
#pragma unroll
        for (int nf = 0; nf < 8; ++nf) {
            mma16816(s[nf], qh_[kc][0], qh_[kc][1], qh_[kc][2], qh_[kc][3], bh[nf][0], bh[nf][1]);
            mma16816(s[nf], qh_[kc][0], qh_[kc][1], qh_[kc][2], qh_[kc][3], bl[nf][0], bl[nf][1]);
            mma16816(s[nf], ql_[kc][0], ql_[kc][1], ql_[kc][2], ql_[kc][3], bh[nf][0], bh[nf][1]);
        }
    }

    int r0 = warp * 16 + (lane >> 2), r1 = r0 + 8;
    int c0base = (lane & 3) * 2;
    float sum0 = 0.0f, sum1 = 0.0f;
#pragma unroll
    for (int nf = 0; nf < 8; ++nf) {
        int c0 = nf * 8 + c0base, c1 = c0 + 1;
        float p00 = __expf(s[nf][0] + bias_s[((r0 >> 3) - (c0 >> 3) + 7) * 15 + (r0 & 7) - (c0 & 7) + 7]);
        float p01 = __expf(s[nf][1] + bias_s[((r0 >> 3) - (c1 >> 3) + 7) * 15 + (r0 & 7) - (c1 & 7) + 7]);
        float p10 = __expf(s[nf][2] + bias_s[((r1 >> 3) - (c0 >> 3) + 7) * 15 + (r1 & 7) - (c0 & 7) + 7]);
        float p11 = __expf(s[nf][3] + bias_s[((r1 >> 3) - (c1 >> 3) + 7) * 15 + (r1 & 7) - (c1 & 7) + 7]);
        s[nf][0] = p00; s[nf][1] = p01; s[nf][2] = p10; s[nf][3] = p11;
        sum0 += p00 + p01;
        sum1 += p10 + p11;
    }
    sum0 += __shfl_xor_sync(0xffffffffu, sum0, 1);
    sum0 += __shfl_xor_sync(0xffffffffu, sum0, 2);
    sum1 += __shfl_xor_sync(0xffffffffu, sum1, 1);
    sum1 += __shfl_xor_sync(0xffffffffu, sum1, 2);

    uint32_t ph[4][4], pl[4][4];
#pragma unroll
    for (int k2 = 0; k2 < 4; ++k2) {
        split2(s[2 * k2][0],     s[2 * k2][1],     ph[k2][0], pl[k2][0]);
        split2(s[2 * k2][2],     s[2 * k2][3],     ph[k2][1], pl[k2][1]);
        split2(s[2 * k2 + 1][0], s[2 * k2 + 1][1], ph[k2][2], pl[k2][2]);
        split2(s[2 * k2 + 1][2], s[2 * k2 + 1][3], ph[k2][3], pl[k2][3]);
    }

    float o[4][4];
#pragma unroll
    for (int nf = 0; nf < 4; ++nf)
#pragma unroll
        for (int j = 0; j < 4; ++j) o[nf][j] = 0.0f;

#pragma unroll
    for (int k2 = 0; k2 < 4; ++k2) {
        int key = k2 * 16 + ((lane >> 3) & 1) * 8 + (lane & 7);
#pragma unroll
        for (int dp = 0; dp < 2; ++dp) {
            uint32_t ao = (uint32_t)(key * APITCH + dp * 16 + (lane >> 4) * 8) * 2;
            uint32_t vh0, vh1, vh2, vh3, vl0, vl1, vl2, vl3;
            ldsm4t(vh0, vh1, vh2, vh3, sv0 + ao);
            ldsm4t(vl0, vl1, vl2, vl3, sv1 + ao);
            mma16816(o[2 * dp],     ph[k2][0], ph[k2][1], ph[k2][2], ph[k2][3], vh0, vh1);
            mma16816(o[2 * dp],     ph[k2][0], ph[k2][1], ph[k2][2], ph[k2][3], vl0, vl1);
            mma16816(o[2 * dp],     pl[k2][0], pl[k2][1], pl[k2][2], pl[k2][3], vh0, vh1);
            mma16816(o[2 * dp + 1], ph[k2][0], ph[k2][1], ph[k2][2], ph[k2][3], vh2, vh3);
            mma16816(o[2 * dp + 1], ph[k2][0], ph[k2][1], ph[k2][2], ph[k2][3], vl2, vl3);
            mma16816(o[2 * dp + 1], pl[k2][0], pl[k2][1], pl[k2][2], pl[k2][3], vh2, vh3);
        }
    }

    float inv0 = 1.0f / sum0, inv1 = 1.0f / sum1;
    size_t row0 = ((size_t)w * WS2 + r0) * CDIM + h * HD;
    size_t row1 = ((size_t)w * WS2 + r1) * CDIM + h * HD;
#pragma unroll
    for (int nf = 0; nf < 4; ++nf) {
        int d = nf * 8 + c0base;
        uint32_t hi, lo;
        split2(o[nf][0] * inv0, o[nf][1] * inv0, hi, lo);
        *(uint32_t*)(g_ath + row0 + d) = hi;
        *(uint32_t*)(g_atl + row0 + d) = lo;
        split2(o[nf][2] * inv1, o[nf][3] * inv1, hi, lo);
        *(uint32_t*)(g_ath + row1 + d) = hi;
        *(uint32_t*)(g_atl + row1 + d) = lo;
    }
}

// ================= K3: proj GEMM + bias + pixel scatter =================
__global__ __launch_bounds__(NTHR) void k_proj(const float* __restrict__ pb,
                                               float* __restrict__ out) {
    extern __shared__ char smem[];
    uint32_t sb = smem_to_u32(smem);
    int tid = threadIdx.x, mt = blockIdx.x;
    int warp = tid >> 5, lane = tid & 31;
    int mslice = warp >> 1, nslice = warp & 1;

    stage_async(g_wph, g_wpl, sb + OFF_B0, 25600, 64, tid);
    stage_async(g_ath + (size_t)mt * 128 * CDIM, g_atl + (size_t)mt * 128 * CDIM,
                sb + OFF_AH, OFF_AL - OFF_AH, 128, tid);
    CP_COMMIT();
    CP_WAIT0();
    __syncthreads();

    for (int nt = 0; nt < 3; ++nt) {
        uint32_t cur = (nt & 1) ? OFF_B1 : OFF_B0;
        if (nt + 1 < 3) {
            uint32_t nxt = (nt & 1) ? OFF_B0 : OFF_B1;
            stage_async(g_wph + (size_t)(nt + 1) * 64 * CDIM,
                        g_wpl + (size_t)(nt + 1) * 64 * CDIM, sb + nxt, 25600, 64, tid);
            CP_COMMIT();
        }

        float acc[4][4];
        mma_core(sb, cur, mslice, nslice, lane, acc);

#pragma unroll
        for (int half = 0; half < 2; ++half) {
            int p = mt * 128 + mslice * 16 + (lane >> 2) + half * 8;
            int w = p >> 6, t = p & 63;
            int b = w >> 10, wh = (w >> 5) & 31, ww = w & 31;
            int ri = t >> 3, ci = t & 7;
            size_t pix = (size_t)((b << 8) + (wh << 3) + ri) * 256 + (ww << 3) + ci;
            float* o = out + pix * CDIM;
#pragma unroll
            for (int nf = 0; nf < 4; ++nf) {
                int oc = nt * 64 + nslice * 32 + nf * 8 + (lane & 3) * 2;
                float2 bias = *(const float2*)(pb + oc);
                *(float2*)(o + oc) = make_float2(acc[nf][half * 2] + bias.x,
                                                 acc[nf][half * 2 + 1] + bias.y);
            }
        }
        if (nt + 1 < 3) CP_WAIT0();
        __syncthreads();
    }
}

// ================= launch =================
extern "C" void kernel_launch(void* const* d_in, const int* in_sizes, int n_in,
                              void* d_out, int out_size) {
    const float* x     = (const float*)d_in[0];
    const float* qkvw  = (const float*)d_in[1];
    const float* projw = (const float*)d_in[2];
    const float* pb    = (const float*)d_in[3];
    const float* rpb   = (const float*)d_in[4];
    (void)in_sizes; (void)n_in; (void)out_size;

    cudaFuncSetAttribute(k_qkv,  cudaFuncAttributeMaxDynamicSharedMemorySize, GEMM_SMEM);
    cudaFuncSetAttribute(k_proj, cudaFuncAttributeMaxDynamicSharedMemorySize, GEMM_SMEM);

    k_prep<<<768, 192>>>(qkvw, projw);
    k_qkv <<<2048, NTHR, GEMM_SMEM>>>(x);
    k_attn<<<dim3(NHD, NW), 128>>>(rpb);
    k_proj<<<2048, NTHR, GEMM_SMEM>>>(pb, (float*)d_out);
}

// round 17
// speedup vs baseline: 1.9484x; 1.2350x over previous
#include <cuda_runtime.h>
#include <cuda_bf16.h>
#include <cuda_fp16.h>
#include <cstdint>

#define NW   4096
#define NHD  6
#define HD   32
#define CDIM 192
#define WS2  64

// GEMM smem layout (fp16, row pitch 200 elems, ldmatrix conflict-free)
#define PITCH  200
#define OFF_AH 0
#define OFF_AL 51200
#define OFF_B0 102400
#define OFF_B1 128000
#define GEMM_SMEM 153600
#define NTHR 512

// ---- scratch ----
__device__ __nv_bfloat16 g_qh[(size_t)NW * NHD * WS2 * HD], g_ql[(size_t)NW * NHD * WS2 * HD];
__device__ __nv_bfloat16 g_kh[(size_t)NW * NHD * WS2 * HD], g_kl[(size_t)NW * NHD * WS2 * HD];
__device__ __nv_bfloat16 g_vh[(size_t)NW * NHD * WS2 * HD], g_vl[(size_t)NW * NHD * WS2 * HD];
__device__ __half g_ath[(size_t)NW * WS2 * CDIM], g_atl[(size_t)NW * WS2 * CDIM];
__device__ __half g_wq16[576 * 192];      // qkv weights fp16 (q rows pre-scaled)
__device__ __half g_wp16[192 * 192];      // proj weights fp16

// ================= helpers =================
__device__ __forceinline__ uint32_t smem_to_u32(const void* p) {
    uint32_t a;
    asm("{ .reg .u64 t; cvta.to.shared.u64 t, %1; cvt.u32.u64 %0, t; }" : "=r"(a) : "l"(p));
    return a;
}
__device__ __forceinline__ void ldsm4(uint32_t& r0, uint32_t& r1, uint32_t& r2, uint32_t& r3,
                                      uint32_t addr) {
    asm volatile("ldmatrix.sync.aligned.m8n8.x4.shared.b16 {%0,%1,%2,%3}, [%4];"
                 : "=r"(r0), "=r"(r1), "=r"(r2), "=r"(r3) : "r"(addr));
}
__device__ __forceinline__ void ldsm4t(uint32_t& r0, uint32_t& r1, uint32_t& r2, uint32_t& r3,
                                       uint32_t addr) {
    asm volatile("ldmatrix.sync.aligned.m8n8.x4.trans.shared.b16 {%0,%1,%2,%3}, [%4];"
                 : "=r"(r0), "=r"(r1), "=r"(r2), "=r"(r3) : "r"(addr));
}
__device__ __forceinline__ void mma_bf16(float* c, uint32_t a0, uint32_t a1, uint32_t a2,
                                         uint32_t a3, uint32_t b0, uint32_t b1) {
    asm volatile("mma.sync.aligned.m16n8k16.row.col.f32.bf16.bf16.f32 "
                 "{%0,%1,%2,%3}, {%4,%5,%6,%7}, {%8,%9}, {%0,%1,%2,%3};"
                 : "+f"(c[0]), "+f"(c[1]), "+f"(c[2]), "+f"(c[3])
                 : "r"(a0), "r"(a1), "r"(a2), "r"(a3), "r"(b0), "r"(b1));
}
__device__ __forceinline__ void mma_f16(float* c, uint32_t a0, uint32_t a1, uint32_t a2,
                                        uint32_t a3, uint32_t b0, uint32_t b1) {
    asm volatile("mma.sync.aligned.m16n8k16.row.col.f32.f16.f16.f32 "
                 "{%0,%1,%2,%3}, {%4,%5,%6,%7}, {%8,%9}, {%0,%1,%2,%3};"
                 : "+f"(c[0]), "+f"(c[1]), "+f"(c[2]), "+f"(c[3])
                 : "r"(a0), "r"(a1), "r"(a2), "r"(a3), "r"(b0), "r"(b1));
}
#define CP_ASYNC16(dst, src) \
    asm volatile("cp.async.cg.shared.global [%0], [%1], 16;" :: "r"(dst), "l"(src) : "memory")
#define CP_COMMIT() asm volatile("cp.async.commit_group;" ::: "memory")
#define CP_WAIT0()  asm volatile("cp.async.wait_group 0;" ::: "memory")

// fp32 pair -> bf16x2 hi/lo
__device__ __forceinline__ void split2(float a, float b, uint32_t& hi, uint32_t& lo) {
    __nv_bfloat162 h = __floats2bfloat162_rn(a, b);
    float2 f = __bfloat1622float2(h);
    __nv_bfloat162 l = __floats2bfloat162_rn(a - f.x, b - f.y);
    hi = *(uint32_t*)&h;
    lo = *(uint32_t*)&l;
}
// fp32 pair -> half2 hi/lo
__device__ __forceinline__ void split2h(float a, float b, uint32_t& hi, uint32_t& lo) {
    __half2 h = __floats2half2_rn(a, b);
    float2 f = __half22float2(h);
    __half2 l = __floats2half2_rn(a - f.x, b - f.y);
    hi = *(uint32_t*)&h;
    lo = *(uint32_t*)&l;
}

// ================= prep: weights fp32 -> fp16 (q rows pre-scaled) =================
__global__ void k_prep(const float* __restrict__ qkvw, const float* __restrict__ projw) {
    int o = blockIdx.x, c = threadIdx.x;
    if (o < 576) {
        float v = qkvw[o * 192 + c];
        if (o < 192) v *= 0.17677669529663687f;
        g_wq16[o * 192 + c] = __float2half_rn(v);
    } else {
        g_wp16[(o - 576) * 192 + c] = __float2half_rn(projw[(o - 576) * 192 + c]);
    }
}

// ================= staging =================
// fp32 8-group -> fp16 hi/lo
__device__ __forceinline__ void cvt8h(float4 v0, float4 v1, uint4& hi, uint4& lo) {
    __half2 h0 = __floats2half2_rn(v0.x, v0.y);
    __half2 h1 = __floats2half2_rn(v0.z, v0.w);
    __half2 h2 = __floats2half2_rn(v1.x, v1.y);
    __half2 h3 = __floats2half2_rn(v1.z, v1.w);
    float2 f0 = __half22float2(h0), f1 = __half22float2(h1);
    float2 f2 = __half22float2(h2), f3 = __half22float2(h3);
    __half2 l0 = __floats2half2_rn(v0.x - f0.x, v0.y - f0.y);
    __half2 l1 = __floats2half2_rn(v0.z - f1.x, v0.w - f1.y);
    __half2 l2 = __floats2half2_rn(v1.x - f2.x, v1.y - f2.y);
    __half2 l3 = __floats2half2_rn(v1.z - f3.x, v1.w - f3.y);
    hi = make_uint4(*(uint32_t*)&h0, *(uint32_t*)&h1, *(uint32_t*)&h2, *(uint32_t*)&h3);
    lo = make_uint4(*(uint32_t*)&l0, *(uint32_t*)&l1, *(uint32_t*)&l2, *(uint32_t*)&l3);
}

__device__ __forceinline__ void stage_rows_f32h(const float* __restrict__ src, int nrows,
                                                char* dh, char* dl, int tid) {
    int groups = nrows * 24;
    for (int idx = tid; idx < groups; idx += NTHR) {
        int r = idx / 24, g = idx - r * 24;
        const float4* p = (const float4*)(src + (size_t)r * CDIM + g * 8);
        uint4 hi, lo;
        cvt8h(p[0], p[1], hi, lo);
        uint32_t o = (uint32_t)(r * PITCH + g * 8) * 2;
        *(uint4*)(dh + o) = hi;
        *(uint4*)(dl + o) = lo;
    }
}

// single 16-bit plane -> smem via cp.async
__device__ __forceinline__ void stage_async_one(const void* __restrict__ src,
                                                uint32_t dbuf, int nrows, int tid) {
    int groups = nrows * 24;
    for (int idx = tid; idx < groups; idx += NTHR) {
        int r = idx / 24, g = idx - r * 24;
        CP_ASYNC16(dbuf + (uint32_t)(r * PITCH + g * 8) * 2,
                   (const char*)src + (size_t)r * 384 + g * 16);
    }
}
// hi/lo 16-bit planes -> smem via cp.async
__device__ __forceinline__ void stage_async_hl(const void* __restrict__ sh,
                                               const void* __restrict__ sl,
                                               uint32_t dh, uint32_t dl, int nrows, int tid) {
    int groups = nrows * 24;
    for (int idx = tid; idx < groups; idx += NTHR) {
        int r = idx / 24, g = idx - r * 24;
        uint32_t o = (uint32_t)(r * PITCH + g * 8) * 2;
        CP_ASYNC16(dh + o, (const char*)sh + (size_t)r * 384 + g * 16);
        CP_ASYNC16(dl + o, (const char*)sl + (size_t)r * 384 + g * 16);
    }
}

// ================= GEMM warp core: 16x32/warp, K=192, fp16 2-term, SW-pipelined =================
__device__ __forceinline__ void ld_frags2(uint32_t aAh, uint32_t aAl, uint32_t aB, uint32_t ko,
                                          uint32_t ah[4], uint32_t al[4], uint32_t b[4][2]) {
    ldsm4(ah[0], ah[1], ah[2], ah[3], aAh + ko);
    ldsm4(al[0], al[1], al[2], al[3], aAl + ko);
#pragma unroll
    for (int np = 0; np < 2; ++np)
        ldsm4(b[2 * np][0], b[2 * np][1], b[2 * np + 1][0], b[2 * np + 1][1],
              aB + np * (16 * PITCH * 2) + ko);
}

__device__ __forceinline__ void mma_core(uint32_t sb, uint32_t bbuf, int mslice, int nslice,
                                         int lane, float acc[4][4]) {
#pragma unroll
    for (int nf = 0; nf < 4; ++nf)
#pragma unroll
        for (int j = 0; j < 4; ++j) acc[nf][j] = 0.0f;

    const uint32_t aoff = (uint32_t)((mslice * 16 + (lane & 15)) * PITCH + (lane >> 4) * 8) * 2;
    const uint32_t boff = (uint32_t)((nslice * 32 + (lane & 7) + ((lane >> 4) << 3)) * PITCH
                                     + ((lane >> 3) & 1) * 8) * 2;
    const uint32_t aAh = sb + OFF_AH + aoff, aAl = sb + OFF_AL + aoff;
    const uint32_t aB = sb + bbuf + boff;

    uint32_t ah[2][4], al[2][4], b[2][4][2];
    ld_frags2(aAh, aAl, aB, 0, ah[0], al[0], b[0]);
#pragma unroll
    for (int kc = 0; kc < 12; ++kc) {
        int cur = kc & 1;
        if (kc < 11)
            ld_frags2(aAh, aAl, aB, (kc + 1) * 32, ah[cur ^ 1], al[cur ^ 1], b[cur ^ 1]);
#pragma unroll
        for (int nf = 0; nf < 4; ++nf) {
            mma_f16(acc[nf], ah[cur][0], ah[cur][1], ah[cur][2], ah[cur][3],
                    b[cur][nf][0], b[cur][nf][1]);
            mma_f16(acc[nf], al[cur][0], al[cur][1], al[cur][2], al[cur][3],
                    b[cur][nf][0], b[cur][nf][1]);
        }
    }
}

// ================= K1: QKV GEMM -> bf16 hi/lo q/k/v planes =================
__global__ __launch_bounds__(NTHR) void k_qkv(const float* __restrict__ x) {
    extern __shared__ char smem[];
    uint32_t sb = smem_to_u32(smem);
    int tid = threadIdx.x, mt = blockIdx.x;
    int warp = tid >> 5, lane = tid & 31;
    int mslice = warp >> 1, nslice = warp & 1;

    stage_async_one(g_wq16, sb + OFF_B0, 64, tid);
    CP_COMMIT();
    stage_rows_f32h(x + (size_t)mt * 128 * CDIM, 128, smem + OFF_AH, smem + OFF_AL, tid);
    CP_WAIT0();
    __syncthreads();

    for (int nt = 0; nt < 9; ++nt) {
        uint32_t cur = (nt & 1) ? OFF_B1 : OFF_B0;
        if (nt + 1 < 9) {
            uint32_t nxt = (nt & 1) ? OFF_B0 : OFF_B1;
            stage_async_one(g_wq16 + (size_t)(nt + 1) * 64 * CDIM, sb + nxt, 64, tid);
            CP_COMMIT();
        }

        float acc[4][4];
        mma_core(sb, cur, mslice, nslice, lane, acc);

        int which = nt / 3;
        int rem0 = (nt - which * 3) * 64 + nslice * 32;
        __nv_bfloat16* dh = (which == 0) ? g_qh : (which == 1) ? g_kh : g_vh;
        __nv_bfloat16* dl = (which == 0) ? g_ql : (which == 1) ? g_kl : g_vl;
#pragma unroll
        for (int half = 0; half < 2; ++half) {
            int p = mt * 128 + mslice * 16 + (lane >> 2) + half * 8;
            int b = p >> 16, y = (p >> 8) & 255, xc = p & 255;
            int w = (b << 10) | ((y >> 3) << 5) | (xc >> 3);
            int t = ((y & 7) << 3) | (xc & 7);
            size_t base = ((size_t)(w * NHD)) * 2048 + t * 32;
#pragma unroll
            for (int nf = 0; nf < 4; ++nf) {
                int rem = rem0 + nf * 8 + (lane & 3) * 2;
                int h = rem >> 5, d = rem & 31;
                uint32_t hi, lo;
                split2(acc[nf][half * 2], acc[nf][half * 2 + 1], hi, lo);
                size_t e = base + (size_t)h * 2048 + d;
                *(uint32_t*)(dh + e) = hi;
                *(uint32_t*)(dl + e) = lo;
            }
        }
        if (nt + 1 < 9) CP_WAIT0();
        __syncthreads();
    }
}

// ================= K2: tensorized windowed attention (bf16 3-term; fp16 output) =================
#define APITCH 40
__global__ __launch_bounds__(128) void k_attn(const float* __restrict__ rpb) {
    __shared__ __align__(16) __nv_bfloat16 smQ[2][64 * APITCH];
    __shared__ __align__(16) __nv_bfloat16 smK[2][64 * APITCH];
    __shared__ __align__(16) __nv_bfloat16 smV[2][64 * APITCH];
    __shared__ float bias_s[240];

    int h = blockIdx.x, w = blockIdx.y;
    int tid = threadIdx.x, warp = tid >> 5, lane = tid & 31;
    size_t base = ((size_t)(w * NHD + h)) * 2048;

    {
        const __nv_bfloat16* srcs[6] = {g_qh + base, g_ql + base, g_kh + base,
                                        g_kl + base, g_vh + base, g_vl + base};
        uint32_t dsts[6] = {smem_to_u32(smQ[0]), smem_to_u32(smQ[1]),
                            smem_to_u32(smK[0]), smem_to_u32(smK[1]),
                            smem_to_u32(smV[0]), smem_to_u32(smV[1])};
#pragma unroll
        for (int tl = 0; tl < 6; ++tl) {
#pragma unroll
            for (int i = 0; i < 2; ++i) {
                int idx = i * 128 + tid;
                int r = idx >> 2, seg = idx & 3;
                CP_ASYNC16(dsts[tl] + (uint32_t)(r * APITCH + seg * 8) * 2,
                           srcs[tl] + r * 32 + seg * 8);
            }
        }
        CP_COMMIT();
    }
    for (int i = tid; i < 225; i += 128) bias_s[i] = rpb[i * NHD + h];
    CP_WAIT0();
    __syncthreads();

    uint32_t sq0 = smem_to_u32(smQ[0]), sq1 = smem_to_u32(smQ[1]);
    uint32_t sk0 = smem_to_u32(smK[0]), sk1 = smem_to_u32(smK[1]);
    uint32_t sv0 = smem_to_u32(smV[0]), sv1 = smem_to_u32(smV[1]);

    uint32_t qh_[2][4], ql_[2][4];
    const uint32_t qoff = (uint32_t)((warp * 16 + (lane & 15)) * APITCH + (lane >> 4) * 8) * 2;
#pragma unroll
    for (int kc = 0; kc < 2; ++kc) {
        ldsm4(qh_[kc][0], qh_[kc][1], qh_[kc][2], qh_[kc][3], sq0 + qoff + kc * 32);
        ldsm4(ql_[kc][0], ql_[kc][1], ql_[kc][2], ql_[kc][3], sq1 + qoff + kc * 32);
    }

    float s[8][4];
#pragma unroll
    for (int nf = 0; nf < 8; ++nf)
#pragma unroll
        for (int j = 0; j < 4; ++j) s[nf][j] = 0.0f;

    const uint32_t koff = (uint32_t)(((lane & 7) + ((lane >> 4) << 3)) * APITCH
                                     + ((lane >> 3) & 1) * 8) * 2;
#pragma unroll
    for (int kc = 0; kc < 2; ++kc) {
        uint32_t bh[8][2], bl[8][2];
#pragma unroll
        for (int np = 0; np < 4; ++np) {
            uint32_t ao = koff + (uint32_t)(np * 16 * APITCH) * 2 + kc * 32;
            ldsm4(bh[2 * np][0], bh[2 * np][1], bh[2 * np + 1][0], bh[2 * np + 1][1], sk0 + ao);
            ldsm4(bl[2 * np][0], bl[2 * np][1], bl[2 * np + 1][0], bl[2 * np + 1][1], sk1 + ao);
        }
#pragma unroll
        for (int nf = 0; nf < 8; ++nf) {
            mma_bf16(s[nf], qh_[kc][0], qh_[kc][1], qh_[kc][2], qh_[kc][3], bh[nf][0], bh[nf][1]);
            mma_bf16(s[nf], qh_[kc][0], qh_[kc][1], qh_[kc][2], qh_[kc][3], bl[nf][0], bl[nf][1]);
            mma_bf16(s[nf], ql_[kc][0], ql_[kc][1], ql_[kc][2], ql_[kc][3], bh[nf][0], bh[nf][1]);
        }
    }

    int r0 = warp * 16 + (lane >> 2), r1 = r0 + 8;
    int c0base = (lane & 3) * 2;
    float sum0 = 0.0f, sum1 = 0.0f;
#pragma unroll
    for (int nf = 0; nf < 8; ++nf) {
        int c0 = nf * 8 + c0base, c1 = c0 + 1;
        float p00 = __expf(s[nf][0] + bias_s[((r0 >> 3) - (c0 >> 3) + 7) * 15 + (r0 & 7) - (c0 & 7) + 7]);
        float p01 = __expf(s[nf][1] + bias_s[((r0 >> 3) - (c1 >> 3) + 7) * 15 + (r0 & 7) - (c1 & 7) + 7]);
        float p10 = __expf(s[nf][2] + bias_s[((r1 >> 3) - (c0 >> 3) + 7) * 15 + (r1 & 7) - (c0 & 7) + 7]);
        float p11 = __expf(s[nf][3] + bias_s[((r1 >> 3) - (c1 >> 3) + 7) * 15 + (r1 & 7) - (c1 & 7) + 7]);
        s[nf][0] = p00; s[nf][1] = p01; s[nf][2] = p10; s[nf][3] = p11;
        sum0 += p00 + p01;
        sum1 += p10 + p11;
    }
    sum0 += __shfl_xor_sync(0xffffffffu, sum0, 1);
    sum0 += __shfl_xor_sync(0xffffffffu, sum0, 2);
    sum1 += __shfl_xor_sync(0xffffffffu, sum1, 1);
    sum1 += __shfl_xor_sync(0xffffffffu, sum1, 2);

    uint32_t ph[4][4], pl[4][4];
#pragma unroll
    for (int k2 = 0; k2 < 4; ++k2) {
        split2(s[2 * k2][0],     s[2 * k2][1],     ph[k2][0], pl[k2][0]);
        split2(s[2 * k2][2],     s[2 * k2][3],     ph[k2][1], pl[k2][1]);
        split2(s[2 * k2 + 1][0], s[2 * k2 + 1][1], ph[k2][2], pl[k2][2]);
        split2(s[2 * k2 + 1][2], s[2 * k2 + 1][3], ph[k2][3], pl[k2][3]);
    }

    float o[4][4];
#pragma unroll
    for (int nf = 0; nf < 4; ++nf)
#pragma unroll
        for (int j = 0; j < 4; ++j) o[nf][j] = 0.0f;

#pragma unroll
    for (int k2 = 0; k2 < 4; ++k2) {
        int key = k2 * 16 + ((lane >> 3) & 1) * 8 + (lane & 7);
#pragma unroll
        for (int dp = 0; dp < 2; ++dp) {
            uint32_t ao = (uint32_t)(key * APITCH + dp * 16 + (lane >> 4) * 8) * 2;
            uint32_t vh0, vh1, vh2, vh3, vl0, vl1, vl2, vl3;
            ldsm4t(vh0, vh1, vh2, vh3, sv0 + ao);
            ldsm4t(vl0, vl1, vl2, vl3, sv1 + ao);
            mma_bf16(o[2 * dp],     ph[k2][0], ph[k2][1], ph[k2][2], ph[k2][3], vh0, vh1);
            mma_bf16(o[2 * dp],     ph[k2][0], ph[k2][1], ph[k2][2], ph[k2][3], vl0, vl1);
            mma_bf16(o[2 * dp],     pl[k2][0], pl[k2][1], pl[k2][2], pl[k2][3], vh0, vh1);
            mma_bf16(o[2 * dp + 1], ph[k2][0], ph[k2][1], ph[k2][2], ph[k2][3], vh2, vh3);
            mma_bf16(o[2 * dp + 1], ph[k2][0], ph[k2][1], ph[k2][2], ph[k2][3], vl2, vl3);
            mma_bf16(o[2 * dp + 1], pl[k2][0], pl[k2][1], pl[k2][2], pl[k2][3], vh2, vh3);
        }
    }

    float inv0 = 1.0f / sum0, inv1 = 1.0f / sum1;
    size_t row0 = ((size_t)w * WS2 + r0) * CDIM + h * HD;
    size_t row1 = ((size_t)w * WS2 + r1) * CDIM + h * HD;
#pragma unroll
    for (int nf = 0; nf < 4; ++nf) {
        int d = nf * 8 + c0base;
        uint32_t hi, lo;
        split2h(o[nf][0] * inv0, o[nf][1] * inv0, hi, lo);
        *(uint32_t*)(g_ath + row0 + d) = hi;
        *(uint32_t*)(g_atl + row0 + d) = lo;
        split2h(o[nf][2] * inv1, o[nf][3] * inv1, hi, lo);
        *(uint32_t*)(g_ath + row1 + d) = hi;
        *(uint32_t*)(g_atl + row1 + d) = lo;
    }
}

// ================= K3: proj GEMM + bias + pixel scatter =================
__global__ __launch_bounds__(NTHR) void k_proj(const float* __restrict__ pb,
                                               float* __restrict__ out) {
    extern __shared__ char smem[];
    uint32_t sb = smem_to_u32(smem);
    int tid = threadIdx.x, mt = blockIdx.x;
    int warp = tid >> 5, lane = tid & 31;
    int mslice = warp >> 1, nslice = warp & 1;

    stage_async_one(g_wp16, sb + OFF_B0, 64, tid);
    stage_async_hl(g_ath + (size_t)mt * 128 * CDIM, g_atl + (size_t)mt * 128 * CDIM,
                   sb + OFF_AH, sb + OFF_AL, 128, tid);
    CP_COMMIT();
    CP_WAIT0();
    __syncthreads();

    for (int nt = 0; nt < 3; ++nt) {
        uint32_t cur = (nt & 1) ? OFF_B1 : OFF_B0;
        if (nt + 1 < 3) {
            uint32_t nxt = (nt & 1) ? OFF_B0 : OFF_B1;
            stage_async_one(g_wp16 + (size_t)(nt + 1) * 64 * CDIM, sb + nxt, 64, tid);
            CP_COMMIT();
        }

        float acc[4][4];
        mma_core(sb, cur, mslice, nslice, lane, acc);

#pragma unroll
        for (int half = 0; half < 2; ++half) {
            int p = mt * 128 + mslice * 16 + (lane >> 2) + half * 8;
            int w = p >> 6, t = p & 63;
            int b = w >> 10, wh = (w >> 5) & 31, ww = w & 31;
            int ri = t >> 3, ci = t & 7;
            size_t pix = (size_t)((b << 8) + (wh << 3) + ri) * 256 + (ww << 3) + ci;
            float* o = out + pix * CDIM;
#pragma unroll
            for (int nf = 0; nf < 4; ++nf) {
                int oc = nt * 64 + nslice * 32 + nf * 8 + (lane & 3) * 2;
                float2 bias = *(const float2*)(pb + oc);
                *(float2*)(o + oc) = make_float2(acc[nf][half * 2] + bias.x,
                                                 acc[nf][half * 2 + 1] + bias.y);
            }
        }
        if (nt + 1 < 3) CP_WAIT0();
        __syncthreads();
    }
}

// ================= launch =================
extern "C" void kernel_launch(void* const* d_in, const int* in_sizes, int n_in,
                              void* d_out, int out_size) {
    const float* x     = (const float*)d_in[0];
    const float* qkvw  = (const float*)d_in[1];
    const float* projw = (const float*)d_in[2];
    const float* pb    = (const float*)d_in[3];
    const float* rpb   = (const float*)d_in[4];
    (void)in_sizes; (void)n_in; (void)out_size;

    cudaFuncSetAttribute(k_qkv,  cudaFuncAttributeMaxDynamicSharedMemorySize, GEMM_SMEM);
    cudaFuncSetAttribute(k_proj, cudaFuncAttributeMaxDynamicSharedMemorySize, GEMM_SMEM);

    k_prep<<<768, 192>>>(qkvw, projw);
    k_qkv <<<2048, NTHR, GEMM_SMEM>>>(x);
    k_attn<<<dim3(NHD, NW), 128>>>(rpb);
    k_proj<<<2048, NTHR, GEMM_SMEM>>>(pb, (float*)d_out);
}